// round 7
// baseline (speedup 1.0000x reference)
#include <cuda_runtime.h>
#include <cuda_bf16.h>
#include <math.h>

// Problem constants
#define BB 64        // batch
#define TT 32        // max_len
#define HH 1024      // hidden
#define VV 32000     // vocab
#define GG 3072      // 3*H

typedef __nv_bfloat16 bf16;

// ---------------- scratch (static device globals; no allocation) ----------------
__device__ float g_gi[TT * BB * GG];         // [t][b][3H]   ~25 MB
__device__ float g_hs[BB * TT * HH];         // [b][t][h]    ~8.4 MB
__device__ float g_henc[BB * HH];            // fp32 copy of encoder_hidden
__device__ float g_h0[BB * HH];
__device__ float g_h1[BB * HH];
__device__ int   g_is_bf16;                  // 1 if float tensors are bf16
__device__ int   g_tgt64;                    // 1 if target tensor is int64

// ---------------- dtype-flexible loads (elem_idx must be multiple of 8) -------
__device__ __forceinline__ void ld8_bf16(const bf16* p, float* f) {
    union { uint4 u; __nv_bfloat162 h[4]; } v;
    v.u = *(const uint4*)p;
#pragma unroll
    for (int i = 0; i < 4; i++) {
        float2 t = __bfloat1622float2(v.h[i]);
        f[2 * i] = t.x; f[2 * i + 1] = t.y;
    }
}
__device__ __forceinline__ void ld8_any(const void* base, size_t elem_idx,
                                        float* f, int isbf) {
    if (isbf) {
        ld8_bf16((const bf16*)base + elem_idx, f);
    } else {
        const float4* p = (const float4*)((const float*)base + elem_idx);
        float4 a = p[0], b = p[1];
        f[0] = a.x; f[1] = a.y; f[2] = a.z; f[3] = a.w;
        f[4] = b.x; f[5] = b.y; f[6] = b.z; f[7] = b.w;
    }
}
__device__ __forceinline__ float ld1_any(const void* base, size_t i, int isbf) {
    return isbf ? __bfloat162float(((const bf16*)base)[i]) : ((const float*)base)[i];
}

// =====================================================================
// K-1: detect dtypes from data (deterministic, device-side, capturable)
// =====================================================================
__global__ void detect_kernel(const void* emb, const int* target)
{
    if (threadIdx.x != 0 || blockIdx.x != 0) return;
    const unsigned short* h = (const unsigned short*)emb;
    int plaus = 0;
    for (int i = 0; i < 512; i++) {
        unsigned short u = h[i];
        int e = (u >> 7) & 0xFF;
        if ((u & 0x7FFF) == 0 || (e >= 112 && e <= 142)) plaus++;
    }
    g_is_bf16 = (plaus >= 410);   // fp32 N(0,1) data scores ~56%; bf16 ~100%
    int zeros_odd = 0;
    for (int i = 0; i < 64; i++) if (target[2 * i + 1] == 0) zeros_odd++;
    g_tgt64 = (zeros_odd >= 62);
}

// =====================================================================
// K0: convert encoder_hidden -> g_henc (fp32)
// =====================================================================
__global__ void init_h_kernel(const void* __restrict__ enc_hidden)
{
    int i = blockIdx.x * blockDim.x + threadIdx.x;
    if (i < BB * HH) g_henc[i] = ld1_any(enc_hidden, i, g_is_bf16);
}

// =====================================================================
// K1: gi[t,b,g] = sum_h relu(emb[tok(b,t),h]) * W_ih[g,h] + b_ih[g]
// M = T*B = 2048 (r = t*B + b), N = 3072, K = 1024.  128x128x16, 256 thr
// =====================================================================
__global__ __launch_bounds__(256) void gi_gemm_kernel(
    const void* __restrict__ emb, const void* __restrict__ Wih,
    const void* __restrict__ bih, const int* __restrict__ target,
    const int* __restrict__ sos)
{
    __shared__ float As[16][128];
    __shared__ float Bs[16][128];
    __shared__ int   toks[128];

    const int tid = threadIdx.x;
    const int isbf = g_is_bf16;
    const int ty = tid >> 4, tx = tid & 15;
    const int rowBase = blockIdx.y * 128;
    const int colBase = blockIdx.x * 128;

    if (tid < 128) {
        int r = rowBase + tid;
        int t = r >> 6;          // r = t*64 + b
        int b = r & 63;
        int tok;
        if (t == 0) tok = sos ? sos[0] : 0;
        else {
            int idx = b * TT + (t - 1);
            tok = g_tgt64 ? target[2 * idx] : target[idx];
        }
        toks[tid] = min(max(tok, 0), VV - 1);   // crash-proof clamp
    }
    __syncthreads();

    float acc[8][8];
#pragma unroll
    for (int i = 0; i < 8; i++)
#pragma unroll
        for (int j = 0; j < 8; j++) acc[i][j] = 0.f;

    const int lm = tid >> 1;          // 0..127
    const int lk = (tid & 1) * 8;     // 0 or 8

    for (int kt = 0; kt < HH / 16; kt++) {
        {   // A tile: gather emb rows via toks, fuse relu
            float f[8];
            ld8_any(emb, (size_t)toks[lm] * HH + kt * 16 + lk, f, isbf);
#pragma unroll
            for (int i = 0; i < 8; i++) As[lk + i][lm] = fmaxf(f[i], 0.f);
        }
        {   // B tile: W_ih rows
            float f[8];
            ld8_any(Wih, (size_t)(colBase + lm) * HH + kt * 16 + lk, f, isbf);
#pragma unroll
            for (int i = 0; i < 8; i++) Bs[lk + i][lm] = f[i];
        }
        __syncthreads();
#pragma unroll
        for (int k = 0; k < 16; k++) {
            float a[8], b[8];
            *(float4*)(a)     = *(const float4*)&As[k][ty * 8];
            *(float4*)(a + 4) = *(const float4*)&As[k][ty * 8 + 4];
            *(float4*)(b)     = *(const float4*)&Bs[k][tx * 8];
            *(float4*)(b + 4) = *(const float4*)&Bs[k][tx * 8 + 4];
#pragma unroll
            for (int i = 0; i < 8; i++)
#pragma unroll
                for (int j = 0; j < 8; j++) acc[i][j] = fmaf(a[i], b[j], acc[i][j]);
        }
        __syncthreads();
    }

#pragma unroll
    for (int i = 0; i < 8; i++) {
        int r = rowBase + ty * 8 + i;
#pragma unroll
        for (int j = 0; j < 8; j++) {
            int g = colBase + tx * 8 + j;
            g_gi[(size_t)r * GG + g] = acc[i][j] + ld1_any(bih, g, isbf);
        }
    }
}

// =====================================================================
// K2: one GRU step. Block: 64 b x 8 hidden units (j), 3 gates. 128 blk x 128 thr
// (w_s loader: 48 threads x 8 floats = 384 = 3*8*16 exactly; gt <= 2)
// =====================================================================
__global__ __launch_bounds__(128) void gru_step_kernel(
    const void* __restrict__ Whh, const void* __restrict__ bhh, int t)
{
    const float* h_in  = (t == 0) ? g_henc : ((t & 1) ? g_h0 : g_h1);
    float*       h_out = (t & 1) ? g_h1 : g_h0;

    __shared__ float h_s[16][64];
    __shared__ float w_s[3][16][8];

    const int tid = threadIdx.x;
    const int isbf = g_is_bf16;
    const int jj = tid & 7;
    const int b0 = (tid >> 3) * 4;
    const int j0 = blockIdx.x * 8;

    float accr[4] = {0,0,0,0}, accz[4] = {0,0,0,0}, accn[4] = {0,0,0,0};

    for (int kt = 0; kt < HH / 16; kt++) {
        // h tile: 64 b x 16 k (fp32 source)
#pragma unroll
        for (int it = 0; it < 2; it++) {
            int idx = tid + it * 128;
            int b = idx >> 2;
            int kq = (idx & 3) * 4;
            float4 v = *(const float4*)(h_in + (size_t)b * HH + kt * 16 + kq);
            h_s[kq + 0][b] = v.x; h_s[kq + 1][b] = v.y;
            h_s[kq + 2][b] = v.z; h_s[kq + 3][b] = v.w;
        }
        // W_hh tile: 3 gates x 8 j x 16 k = 384 elems -> 48 loads of 8
        if (tid < 48) {
            int rs = tid >> 1;            // 0..23 = gate*8 + j
            int kq = (tid & 1) * 8;
            int gt = rs >> 3;             // 0..2
            int j = rs & 7;
            float f[8];
            ld8_any(Whh, (size_t)(gt * HH + j0 + j) * HH + kt * 16 + kq, f, isbf);
#pragma unroll
            for (int i = 0; i < 8; i++) w_s[gt][kq + i][j] = f[i];
        }
        __syncthreads();
#pragma unroll
        for (int k = 0; k < 16; k++) {
            float wr = w_s[0][k][jj], wz = w_s[1][k][jj], wn = w_s[2][k][jj];
            float4 hv = *(const float4*)&h_s[k][b0];
            accr[0] = fmaf(hv.x, wr, accr[0]); accr[1] = fmaf(hv.y, wr, accr[1]);
            accr[2] = fmaf(hv.z, wr, accr[2]); accr[3] = fmaf(hv.w, wr, accr[3]);
            accz[0] = fmaf(hv.x, wz, accz[0]); accz[1] = fmaf(hv.y, wz, accz[1]);
            accz[2] = fmaf(hv.z, wz, accz[2]); accz[3] = fmaf(hv.w, wz, accz[3]);
            accn[0] = fmaf(hv.x, wn, accn[0]); accn[1] = fmaf(hv.y, wn, accn[1]);
            accn[2] = fmaf(hv.z, wn, accn[2]); accn[3] = fmaf(hv.w, wn, accn[3]);
        }
        __syncthreads();
    }

    const int jg = j0 + jj;
    const float br = ld1_any(bhh, jg, isbf);
    const float bz = ld1_any(bhh, HH + jg, isbf);
    const float bn = ld1_any(bhh, 2 * HH + jg, isbf);
#pragma unroll
    for (int i = 0; i < 4; i++) {
        int b = b0 + i;
        const float* girow = g_gi + ((size_t)(t * BB + b)) * GG;
        float ir = girow[jg], iz = girow[HH + jg], inn = girow[2 * HH + jg];
        float ghr = accr[i] + br, ghz = accz[i] + bz, ghn = accn[i] + bn;
        float rg = 1.f / (1.f + expf(-(ir + ghr)));
        float zg = 1.f / (1.f + expf(-(iz + ghz)));
        float ng = tanhf(inn + rg * ghn);
        float hprev = h_in[(size_t)b * HH + jg];
        float hnew = (1.f - zg) * ng + zg * hprev;
        h_out[(size_t)b * HH + jg] = hnew;
        g_hs[((size_t)b * TT + t) * HH + jg] = hnew;   // [b][t][h]
    }
}

// =====================================================================
// K3: logits[r2, v] = sum_h hs[r2,h]*out_W[v,h] + out_b[v]  -> d_out (fp32)
// r2 = b*T + t. M=2048, N=32000, K=1024. 128x128x16, 256 thr
// =====================================================================
__global__ __launch_bounds__(256) void out_gemm_kernel(
    const void* __restrict__ outW, const void* __restrict__ outb,
    float* __restrict__ out)
{
    __shared__ float As[16][128];
    __shared__ float Bs[16][128];

    const int tid = threadIdx.x;
    const int isbf = g_is_bf16;
    const int ty = tid >> 4, tx = tid & 15;
    const int rowBase = blockIdx.y * 128;
    const int colBase = blockIdx.x * 128;

    float acc[8][8];
#pragma unroll
    for (int i = 0; i < 8; i++)
#pragma unroll
        for (int j = 0; j < 8; j++) acc[i][j] = 0.f;

    const int lm = tid >> 1;
    const int lk = (tid & 1) * 8;

    for (int kt = 0; kt < HH / 16; kt++) {
        // A tile from fp32 g_hs
#pragma unroll
        for (int it = 0; it < 2; it++) {
            int idx = tid + it * 256;
            int m = idx >> 2;
            int kq = (idx & 3) * 4;
            const float4 v = *(const float4*)(g_hs + (size_t)(rowBase + m) * HH + kt * 16 + kq);
            As[kq + 0][m] = v.x; As[kq + 1][m] = v.y;
            As[kq + 2][m] = v.z; As[kq + 3][m] = v.w;
        }
        // B tile from out_W
        {
            float f[8];
            ld8_any(outW, (size_t)(colBase + lm) * HH + kt * 16 + lk, f, isbf);
#pragma unroll
            for (int i = 0; i < 8; i++) Bs[lk + i][lm] = f[i];
        }
        __syncthreads();
#pragma unroll
        for (int k = 0; k < 16; k++) {
            float a[8], b[8];
            *(float4*)(a)     = *(const float4*)&As[k][ty * 8];
            *(float4*)(a + 4) = *(const float4*)&As[k][ty * 8 + 4];
            *(float4*)(b)     = *(const float4*)&Bs[k][tx * 8];
            *(float4*)(b + 4) = *(const float4*)&Bs[k][tx * 8 + 4];
#pragma unroll
            for (int i = 0; i < 8; i++)
#pragma unroll
                for (int j = 0; j < 8; j++) acc[i][j] = fmaf(a[i], b[j], acc[i][j]);
        }
        __syncthreads();
    }

#pragma unroll
    for (int i = 0; i < 8; i++) {
        size_t r = rowBase + ty * 8 + i;
#pragma unroll
        for (int j = 0; j < 8; j++) {
            int v = colBase + tx * 8 + j;
            out[r * VV + v] = acc[i][j] + ld1_any(outb, v, isbf);
        }
    }
}

// =====================================================================
// K4: in-place log_softmax over V on fp32 d_out. 1 blk/row
// =====================================================================
__global__ __launch_bounds__(256) void logsoftmax_kernel(float* __restrict__ out)
{
    __shared__ float red[256];
    const int tid = threadIdx.x;
    float* p = out + (size_t)blockIdx.x * VV;
    const float4* p4 = (const float4*)p;
    const int n4 = VV / 4;  // 8000

    float m = -1e30f;
    for (int i = tid; i < n4; i += 256) {
        float4 v = p4[i];
        m = fmaxf(m, fmaxf(fmaxf(v.x, v.y), fmaxf(v.z, v.w)));
    }
    red[tid] = m; __syncthreads();
    for (int s = 128; s > 0; s >>= 1) {
        if (tid < s) red[tid] = fmaxf(red[tid], red[tid + s]);
        __syncthreads();
    }
    m = red[0]; __syncthreads();

    float sum = 0.f;
    for (int i = tid; i < n4; i += 256) {
        float4 v = p4[i];
        sum += expf(v.x - m) + expf(v.y - m) + expf(v.z - m) + expf(v.w - m);
    }
    red[tid] = sum; __syncthreads();
    for (int s = 128; s > 0; s >>= 1) {
        if (tid < s) red[tid] += red[tid + s];
        __syncthreads();
    }
    const float L = m + logf(red[0]);

    float4* w4 = (float4*)p;
    for (int i = tid; i < n4; i += 256) {
        float4 v = w4[i];
        v.x -= L; v.y -= L; v.z -= L; v.w -= L;
        w4[i] = v;
    }
}

// K5: append h_final (t=31 odd -> g_h1) after log_probs, fp32
__global__ void hfinal_kernel(float* __restrict__ out)
{
    int i = blockIdx.x * blockDim.x + threadIdx.x;
    if (i < BB * HH) out[(size_t)BB * TT * VV + i] = g_h1[i];
}

// =====================================================================
// Size-signature input resolution (element counts are dtype-invariant).
// =====================================================================
extern "C" void kernel_launch(void* const* d_in, const int* in_sizes, int n_in,
                              void* d_out, int out_size)
{
    const void* enc_hidden = nullptr;   // 65536
    const int*  target     = nullptr;   // 2048 (LAST; mask precedes it)
    const int*  sos        = nullptr;   // 1 (FIRST)
    const void* emb        = nullptr;   // 32768000 (FIRST)
    const void* outW       = nullptr;   // 32768000 (LAST)
    const void* Wih        = nullptr;   // 3145728 (FIRST)
    const void* Whh        = nullptr;   // 3145728 (LAST)
    const void* bih        = nullptr;   // 3072 (FIRST)
    const void* bhh        = nullptr;   // 3072 (LAST)
    const void* outb       = nullptr;   // 32000

    for (int i = 0; i < n_in; i++) {
        int s = in_sizes[i];
        void* p = d_in[i];
        switch (s) {
            case 65536:     if (!enc_hidden) enc_hidden = p; break;
            case 2048:      target = (const int*)p; break;            // keep last
            case 1:         if (!sos) sos = (const int*)p; break;     // keep first
            case 32768000:  if (!emb) emb = p; else outW = p; break;
            case 3145728:   if (!Wih) Wih = p; else Whh = p; break;
            case 3072:      if (!bih) bih = p; else bhh = p; break;
            case 32000:     outb = p; break;
            default: break; // encoder_outputs (2097152) and input_mask unused
        }
    }
    float* out = (float*)d_out;
    if (!enc_hidden || !target || !emb || !outW || !Wih || !Whh || !bih || !bhh || !outb)
        return;  // contract mismatch -> poisoned output, diagnosable

    // K-1: dtype detection (device-side, deterministic)
    detect_kernel<<<1, 32>>>(emb, target);

    // K0: encoder_hidden -> fp32
    init_h_kernel<<<(BB * HH + 255) / 256, 256>>>(enc_hidden);

    // K1: gi GEMM (2048 x 3072 x 1024)
    {
        dim3 grid(GG / 128, (TT * BB) / 128);  // 24 x 16
        gi_gemm_kernel<<<grid, 256>>>(emb, Wih, bih, target, sos);
    }

    // K2: 32 sequential GRU steps
    for (int t = 0; t < TT; t++) {
        gru_step_kernel<<<128, 128>>>(Whh, bhh, t);
    }

    // K3: output projection (2048 x 32000 x 1024) -> d_out fp32 logits
    {
        dim3 grid(VV / 128, (TT * BB) / 128);  // 250 x 16
        out_gemm_kernel<<<grid, 256>>>(outW, outb, out);
    }

    // K4: in-place log_softmax on fp32 d_out
    logsoftmax_kernel<<<TT * BB, 256>>>(out);

    // K5: h_final, only if the output buffer carries it
    if (out_size >= BB * TT * VV + BB * HH) {
        hfinal_kernel<<<(BB * HH + 255) / 256, 256>>>(out);
    }
}

// round 10
// speedup vs baseline: 2.2219x; 2.2219x over previous
#include <cuda_runtime.h>
#include <cuda_bf16.h>
#include <math.h>
#include <stdint.h>

// Problem constants
#define BB 64        // batch
#define TT 32        // max_len
#define HH 1024      // hidden
#define VV 32000     // vocab
#define GG 3072      // 3*H

typedef __nv_bfloat16 bf16;

// ---------------- scratch (static device globals; no allocation) ----------------
__device__ float g_gi[TT * BB * GG];         // [t][b][3H]   ~25 MB
__device__ float g_hs[BB * TT * HH];         // [b][t][h]    ~8.4 MB
__device__ float g_henc[BB * HH];            // fp32 copy of encoder_hidden
__device__ float g_h0[BB * HH];
__device__ float g_h1[BB * HH];
__device__ bf16  g_hsb[BB * TT * HH];        // bf16 copy of hs for tensor GEMM
__device__ bf16  g_wb[(size_t)VV * HH];      // bf16 copy of out_W ~65 MB
__device__ int   g_is_bf16;
__device__ int   g_tgt64;

// ---------------- dtype-flexible loads -------
__device__ __forceinline__ void ld8_bf16(const bf16* p, float* f) {
    union { uint4 u; __nv_bfloat162 h[4]; } v;
    v.u = *(const uint4*)p;
#pragma unroll
    for (int i = 0; i < 4; i++) {
        float2 t = __bfloat1622float2(v.h[i]);
        f[2 * i] = t.x; f[2 * i + 1] = t.y;
    }
}
__device__ __forceinline__ void ld8_any(const void* base, size_t elem_idx,
                                        float* f, int isbf) {
    if (isbf) {
        ld8_bf16((const bf16*)base + elem_idx, f);
    } else {
        const float4* p = (const float4*)((const float*)base + elem_idx);
        float4 a = p[0], b = p[1];
        f[0] = a.x; f[1] = a.y; f[2] = a.z; f[3] = a.w;
        f[4] = b.x; f[5] = b.y; f[6] = b.z; f[7] = b.w;
    }
}
__device__ __forceinline__ void ld4_any(const void* base, size_t elem_idx,
                                        float* f, int isbf) {
    if (isbf) {
        union { uint2 u; __nv_bfloat162 h[2]; } v;
        v.u = *(const uint2*)((const bf16*)base + elem_idx);
        float2 t0 = __bfloat1622float2(v.h[0]);
        float2 t1 = __bfloat1622float2(v.h[1]);
        f[0] = t0.x; f[1] = t0.y; f[2] = t1.x; f[3] = t1.y;
    } else {
        float4 a = *(const float4*)((const float*)base + elem_idx);
        f[0] = a.x; f[1] = a.y; f[2] = a.z; f[3] = a.w;
    }
}
__device__ __forceinline__ float ld1_any(const void* base, size_t i, int isbf) {
    return isbf ? __bfloat162float(((const bf16*)base)[i]) : ((const float*)base)[i];
}

// =====================================================================
// K-1: dtype detection (deterministic, device-side)
// =====================================================================
__global__ void detect_kernel(const void* emb, const int* target)
{
    if (threadIdx.x != 0 || blockIdx.x != 0) return;
    const unsigned short* h = (const unsigned short*)emb;
    int plaus = 0;
    for (int i = 0; i < 512; i++) {
        unsigned short u = h[i];
        int e = (u >> 7) & 0xFF;
        if ((u & 0x7FFF) == 0 || (e >= 112 && e <= 142)) plaus++;
    }
    g_is_bf16 = (plaus >= 410);
    int zeros_odd = 0;
    for (int i = 0; i < 64; i++) if (target[2 * i + 1] == 0) zeros_odd++;
    g_tgt64 = (zeros_odd >= 62);
}

// =====================================================================
// K0: encoder_hidden -> g_henc (fp32)
// =====================================================================
__global__ void init_h_kernel(const void* __restrict__ enc_hidden)
{
    int i = blockIdx.x * blockDim.x + threadIdx.x;
    if (i < BB * HH) g_henc[i] = ld1_any(enc_hidden, i, g_is_bf16);
}

// =====================================================================
// conv: out_W -> bf16  (32M elems, 8 per thread)
// =====================================================================
__global__ __launch_bounds__(256) void conv_w_kernel(const void* __restrict__ outW)
{
    size_t i = ((size_t)blockIdx.x * 256 + threadIdx.x) * 8;
    if (i >= (size_t)VV * HH) return;
    float f[8];
    ld8_any(outW, i, f, g_is_bf16);
    union { uint4 u; __nv_bfloat162 h[4]; } v;
#pragma unroll
    for (int j = 0; j < 4; j++) v.h[j] = __floats2bfloat162_rn(f[2 * j], f[2 * j + 1]);
    *(uint4*)(g_wb + i) = v.u;
}

// conv: g_hs (fp32) -> g_hsb (bf16)
__global__ __launch_bounds__(256) void conv_hs_kernel()
{
    size_t i = ((size_t)blockIdx.x * 256 + threadIdx.x) * 8;
    if (i >= (size_t)BB * TT * HH) return;
    const float4* p = (const float4*)(g_hs + i);
    float4 a = p[0], b = p[1];
    union { uint4 u; __nv_bfloat162 h[4]; } v;
    v.h[0] = __floats2bfloat162_rn(a.x, a.y);
    v.h[1] = __floats2bfloat162_rn(a.z, a.w);
    v.h[2] = __floats2bfloat162_rn(b.x, b.y);
    v.h[3] = __floats2bfloat162_rn(b.z, b.w);
    *(uint4*)(g_hsb + i) = v.u;
}

// =====================================================================
// K1: gi GEMM (FFMA path)
// =====================================================================
__global__ __launch_bounds__(256) void gi_gemm_kernel(
    const void* __restrict__ emb, const void* __restrict__ Wih,
    const void* __restrict__ bih, const int* __restrict__ target,
    const int* __restrict__ sos)
{
    __shared__ float As[16][128];
    __shared__ float Bs[16][128];
    __shared__ int   toks[128];

    const int tid = threadIdx.x;
    const int isbf = g_is_bf16;
    const int ty = tid >> 4, tx = tid & 15;
    const int rowBase = blockIdx.y * 128;
    const int colBase = blockIdx.x * 128;

    if (tid < 128) {
        int r = rowBase + tid;
        int t = r >> 6;
        int b = r & 63;
        int tok;
        if (t == 0) tok = sos ? sos[0] : 0;
        else {
            int idx = b * TT + (t - 1);
            tok = g_tgt64 ? target[2 * idx] : target[idx];
        }
        toks[tid] = min(max(tok, 0), VV - 1);
    }
    __syncthreads();

    float acc[8][8];
#pragma unroll
    for (int i = 0; i < 8; i++)
#pragma unroll
        for (int j = 0; j < 8; j++) acc[i][j] = 0.f;

    const int lm = tid >> 1;
    const int lk = (tid & 1) * 8;

    for (int kt = 0; kt < HH / 16; kt++) {
        {
            float f[8];
            ld8_any(emb, (size_t)toks[lm] * HH + kt * 16 + lk, f, isbf);
#pragma unroll
            for (int i = 0; i < 8; i++) As[lk + i][lm] = fmaxf(f[i], 0.f);
        }
        {
            float f[8];
            ld8_any(Wih, (size_t)(colBase + lm) * HH + kt * 16 + lk, f, isbf);
#pragma unroll
            for (int i = 0; i < 8; i++) Bs[lk + i][lm] = f[i];
        }
        __syncthreads();
#pragma unroll
        for (int k = 0; k < 16; k++) {
            float a[8], b[8];
            *(float4*)(a)     = *(const float4*)&As[k][ty * 8];
            *(float4*)(a + 4) = *(const float4*)&As[k][ty * 8 + 4];
            *(float4*)(b)     = *(const float4*)&Bs[k][tx * 8];
            *(float4*)(b + 4) = *(const float4*)&Bs[k][tx * 8 + 4];
#pragma unroll
            for (int i = 0; i < 8; i++)
#pragma unroll
                for (int j = 0; j < 8; j++) acc[i][j] = fmaf(a[i], b[j], acc[i][j]);
        }
        __syncthreads();
    }

#pragma unroll
    for (int i = 0; i < 8; i++) {
        int r = rowBase + ty * 8 + i;
#pragma unroll
        for (int j = 0; j < 8; j++) {
            int g = colBase + tx * 8 + j;
            g_gi[(size_t)r * GG + g] = acc[i][j] + ld1_any(bih, g, isbf);
        }
    }
}

// =====================================================================
// K2 v3: GRU step. grid = HH/8 = 128 blocks (8 j's each, all 3 gates),
// 512 threads, K-split-2 (each half of 256 thr covers K=512).
// Per thread: 8 j x 2 b accumulators per gate? No: jj in [0,8), 2 b's.
// =====================================================================
__global__ __launch_bounds__(512) void gru_step_v3(
    const void* __restrict__ Whh, const void* __restrict__ bhh, int t)
{
    const float* h_in  = (t == 0) ? g_henc : ((t & 1) ? g_h0 : g_h1);
    float*       h_out = (t & 1) ? g_h1 : g_h0;

    __shared__ float h_s[2][16][66];    // [half][k][b] padded
    __shared__ float w_s[2][3][16][9];  // [half][gate][k][j] padded
    __shared__ float red[3][8][66];     // [gate][j][b] partials from half 1

    const int tid = threadIdx.x;
    const int isbf = g_is_bf16;
    const int half = tid >> 8;         // 0 or 1
    const int t2 = tid & 255;
    const int jj = t2 & 7;             // j within 8-wide tile
    const int bg = t2 >> 3;            // 0..31
    const int b0 = bg * 2;             // 2 b's per thread
    const int j0 = blockIdx.x * 8;     // 0..1016  (within H)

    float accr[2] = {0,0}, accz[2] = {0,0}, accn[2] = {0,0};

    const int hb  = t2 & 63;           // b for h-tile load
    const int hk4 = (t2 >> 6) * 4;     // k offset (0,4,8,12)

    for (int c8 = 0; c8 < 32; c8++) {
        const int kt = half * 32 + c8;     // 16-k chunk
        // h tile: 16 k x 64 b (each thread: float4 along k)
        {
            float4 v = *(const float4*)(h_in + (size_t)hb * HH + kt * 16 + hk4);
            h_s[half][hk4 + 0][hb] = v.x; h_s[half][hk4 + 1][hb] = v.y;
            h_s[half][hk4 + 2][hb] = v.z; h_s[half][hk4 + 3][hb] = v.w;
        }
        // w tile: 3 gates x 8 j x 16 k = 384 floats -> 96 threads x float4
        if (t2 < 96) {
            int gt = t2 >> 5;              // 0..2
            int rem = t2 & 31;
            int j = rem >> 2;              // 0..7
            int k4 = (rem & 3) * 4;        // 0,4,8,12
            float f[4];
            ld4_any(Whh, (size_t)(gt * HH + j0 + j) * HH + kt * 16 + k4, f, isbf);
#pragma unroll
            for (int i = 0; i < 4; i++) w_s[half][gt][k4 + i][j] = f[i];
        }
        __syncthreads();
#pragma unroll
        for (int k = 0; k < 16; k++) {
            float wr = w_s[half][0][k][jj], wz = w_s[half][1][k][jj], wn = w_s[half][2][k][jj];
            float2 hv = *(const float2*)&h_s[half][k][b0];
            accr[0] = fmaf(hv.x, wr, accr[0]); accr[1] = fmaf(hv.y, wr, accr[1]);
            accz[0] = fmaf(hv.x, wz, accz[0]); accz[1] = fmaf(hv.y, wz, accz[1]);
            accn[0] = fmaf(hv.x, wn, accn[0]); accn[1] = fmaf(hv.y, wn, accn[1]);
        }
        __syncthreads();
    }

    if (half == 1) {
#pragma unroll
        for (int i = 0; i < 2; i++) {
            red[0][jj][b0 + i] = accr[i];
            red[1][jj][b0 + i] = accz[i];
            red[2][jj][b0 + i] = accn[i];
        }
    }
    __syncthreads();
    if (half == 0) {
        const int jg = j0 + jj;            // < HH
        const float br = ld1_any(bhh, jg, isbf);
        const float bz = ld1_any(bhh, HH + jg, isbf);
        const float bn = ld1_any(bhh, 2 * HH + jg, isbf);
#pragma unroll
        for (int i = 0; i < 2; i++) {
            int b = b0 + i;
            const float* girow = g_gi + ((size_t)(t * BB + b)) * GG;
            float ir = girow[jg], iz = girow[HH + jg], inn = girow[2 * HH + jg];
            float ghr = accr[i] + red[0][jj][b] + br;
            float ghz = accz[i] + red[1][jj][b] + bz;
            float ghn = accn[i] + red[2][jj][b] + bn;
            float rg = 1.f / (1.f + expf(-(ir + ghr)));
            float zg = 1.f / (1.f + expf(-(iz + ghz)));
            float ng = tanhf(inn + rg * ghn);
            float hprev = h_in[(size_t)b * HH + jg];
            float hnew = (1.f - zg) * ng + zg * hprev;
            h_out[(size_t)b * HH + jg] = hnew;
            g_hs[((size_t)b * TT + t) * HH + jg] = hnew;
        }
    }
}

// =====================================================================
// K3: projection via bf16 mma.sync (m16n8k16, fp32 accum) -> d_out
// Block 128x128, K-chunk 32, 8 warps (2 m x 4 n), warp tile 64x32.
// =====================================================================
__global__ __launch_bounds__(256) void out_mma_kernel(
    const void* __restrict__ outb, float* __restrict__ out)
{
    __shared__ __align__(16) bf16 As[128][40];
    __shared__ __align__(16) bf16 Bs[128][40];

    const int tid = threadIdx.x;
    const int warp = tid >> 5, lane = tid & 31;
    const int g = lane >> 2, tg = lane & 3;
    const int m0 = (warp >> 2) * 64;
    const int n0 = (warp & 3) * 32;
    const int rowBase = blockIdx.y * 128;
    const int colBase = blockIdx.x * 128;

    float acc[4][4][4];
#pragma unroll
    for (int mt = 0; mt < 4; mt++)
#pragma unroll
        for (int nt = 0; nt < 4; nt++)
#pragma unroll
            for (int i = 0; i < 4; i++) acc[mt][nt][i] = 0.f;

    for (int kt = 0; kt < 32; kt++) {
#pragma unroll
        for (int i = 0; i < 2; i++) {
            int idx = tid + i * 256;
            int r = idx >> 2, kq = (idx & 3) * 8;
            *(uint4*)&As[r][kq] = *(const uint4*)(g_hsb + (size_t)(rowBase + r) * HH + kt * 32 + kq);
            *(uint4*)&Bs[r][kq] = *(const uint4*)(g_wb + (size_t)(colBase + r) * HH + kt * 32 + kq);
        }
        __syncthreads();
#pragma unroll
        for (int kk = 0; kk < 32; kk += 16) {
            uint32_t a[4][4], b[4][2];
#pragma unroll
            for (int mt = 0; mt < 4; mt++) {
                a[mt][0] = *(const uint32_t*)&As[m0 + mt * 16 + g][kk + tg * 2];
                a[mt][1] = *(const uint32_t*)&As[m0 + mt * 16 + g + 8][kk + tg * 2];
                a[mt][2] = *(const uint32_t*)&As[m0 + mt * 16 + g][kk + tg * 2 + 8];
                a[mt][3] = *(const uint32_t*)&As[m0 + mt * 16 + g + 8][kk + tg * 2 + 8];
            }
#pragma unroll
            for (int nt = 0; nt < 4; nt++) {
                b[nt][0] = *(const uint32_t*)&Bs[n0 + nt * 8 + g][kk + tg * 2];
                b[nt][1] = *(const uint32_t*)&Bs[n0 + nt * 8 + g][kk + tg * 2 + 8];
            }
#pragma unroll
            for (int mt = 0; mt < 4; mt++)
#pragma unroll
                for (int nt = 0; nt < 4; nt++)
                    asm volatile(
                        "mma.sync.aligned.m16n8k16.row.col.f32.bf16.bf16.f32 "
                        "{%0,%1,%2,%3}, {%4,%5,%6,%7}, {%8,%9}, {%0,%1,%2,%3};"
                        : "+f"(acc[mt][nt][0]), "+f"(acc[mt][nt][1]),
                          "+f"(acc[mt][nt][2]), "+f"(acc[mt][nt][3])
                        : "r"(a[mt][0]), "r"(a[mt][1]), "r"(a[mt][2]), "r"(a[mt][3]),
                          "r"(b[nt][0]), "r"(b[nt][1]));
        }
        __syncthreads();
    }

    const int isbf = g_is_bf16;
#pragma unroll
    for (int mt = 0; mt < 4; mt++) {
#pragma unroll
        for (int nt = 0; nt < 4; nt++) {
            int c = colBase + n0 + nt * 8 + tg * 2;
            float bx = ld1_any(outb, c, isbf);
            float by = ld1_any(outb, c + 1, isbf);
            size_t r0 = rowBase + m0 + mt * 16 + g;
            *(float2*)&out[r0 * VV + c] =
                make_float2(acc[mt][nt][0] + bx, acc[mt][nt][1] + by);
            *(float2*)&out[(r0 + 8) * VV + c] =
                make_float2(acc[mt][nt][2] + bx, acc[mt][nt][3] + by);
        }
    }
}

// =====================================================================
// K4: in-place log_softmax over V on fp32 d_out. 512 thr/row.
// =====================================================================
__global__ __launch_bounds__(512) void logsoftmax_kernel(float* __restrict__ out)
{
    __shared__ float red[512];
    const int tid = threadIdx.x;
    float* p = out + (size_t)blockIdx.x * VV;
    const float4* p4 = (const float4*)p;
    const int n4 = VV / 4;  // 8000

    float m = -1e30f;
    for (int i = tid; i < n4; i += 512) {
        float4 v = p4[i];
        m = fmaxf(m, fmaxf(fmaxf(v.x, v.y), fmaxf(v.z, v.w)));
    }
    red[tid] = m; __syncthreads();
    for (int s = 256; s > 0; s >>= 1) {
        if (tid < s) red[tid] = fmaxf(red[tid], red[tid + s]);
        __syncthreads();
    }
    m = red[0]; __syncthreads();

    float sum = 0.f;
    for (int i = tid; i < n4; i += 512) {
        float4 v = p4[i];
        sum += expf(v.x - m) + expf(v.y - m) + expf(v.z - m) + expf(v.w - m);
    }
    red[tid] = sum; __syncthreads();
    for (int s = 256; s > 0; s >>= 1) {
        if (tid < s) red[tid] += red[tid + s];
        __syncthreads();
    }
    const float L = m + logf(red[0]);

    float4* w4 = (float4*)p;
    for (int i = tid; i < n4; i += 512) {
        float4 v = w4[i];
        v.x -= L; v.y -= L; v.z -= L; v.w -= L;
        w4[i] = v;
    }
}

// K5: append h_final (t=31 odd -> g_h1), fp32
__global__ void hfinal_kernel(float* __restrict__ out)
{
    int i = blockIdx.x * blockDim.x + threadIdx.x;
    if (i < BB * HH) out[(size_t)BB * TT * VV + i] = g_h1[i];
}

// =====================================================================
extern "C" void kernel_launch(void* const* d_in, const int* in_sizes, int n_in,
                              void* d_out, int out_size)
{
    const void* enc_hidden = nullptr;
    const int*  target     = nullptr;
    const int*  sos        = nullptr;
    const void* emb        = nullptr;
    const void* outW       = nullptr;
    const void* Wih        = nullptr;
    const void* Whh        = nullptr;
    const void* bih        = nullptr;
    const void* bhh        = nullptr;
    const void* outb       = nullptr;

    for (int i = 0; i < n_in; i++) {
        int s = in_sizes[i];
        void* p = d_in[i];
        switch (s) {
            case 65536:     if (!enc_hidden) enc_hidden = p; break;
            case 2048:      target = (const int*)p; break;
            case 1:         if (!sos) sos = (const int*)p; break;
            case 32768000:  if (!emb) emb = p; else outW = p; break;
            case 3145728:   if (!Wih) Wih = p; else Whh = p; break;
            case 3072:      if (!bih) bih = p; else bhh = p; break;
            case 32000:     outb = p; break;
            default: break;
        }
    }
    float* out = (float*)d_out;
    if (!enc_hidden || !target || !emb || !outW || !Wih || !Whh || !bih || !bhh || !outb)
        return;

    detect_kernel<<<1, 32>>>(emb, target);
    init_h_kernel<<<(BB * HH + 255) / 256, 256>>>(enc_hidden);

    // out_W -> bf16
    conv_w_kernel<<<(int)(((size_t)VV * HH / 8 + 255) / 256), 256>>>(outW);

    // gi GEMM
    {
        dim3 grid(GG / 128, (TT * BB) / 128);
        gi_gemm_kernel<<<grid, 256>>>(emb, Wih, bih, target, sos);
    }

    // 32 sequential GRU steps (v3: grid = HH/8 = 128, j-tile 8, K-split 2)
    for (int t = 0; t < TT; t++) {
        gru_step_v3<<<HH / 8, 512>>>(Whh, bhh, t);
    }

    // hs -> bf16
    conv_hs_kernel<<<(int)(((size_t)BB * TT * HH / 8 + 255) / 256), 256>>>();

    // projection via tensor cores -> d_out fp32 logits
    {
        dim3 grid(VV / 128, (TT * BB) / 128);  // 250 x 16
        out_mma_kernel<<<grid, 256>>>(outb, out);
    }

    // in-place log_softmax
    logsoftmax_kernel<<<TT * BB, 512>>>(out);

    if (out_size >= BB * TT * VV + BB * HH) {
        hfinal_kernel<<<(BB * HH + 255) / 256, 256>>>(out);
    }
}

// round 13
// speedup vs baseline: 2.2447x; 1.0102x over previous
#include <cuda_runtime.h>
#include <cuda_bf16.h>
#include <math.h>
#include <stdint.h>

// Problem constants
#define BB 64        // batch
#define TT 32        // max_len
#define HH 1024      // hidden
#define VV 32000     // vocab
#define GG 3072      // 3*H
#define MM 2048      // T*B rows

typedef __nv_bfloat16 bf16;

// ---------------- scratch (static device globals; no allocation) ----------------
__device__ float g_gi[MM * GG];              // [t][b][3H]   ~25 MB
__device__ float g_hs[BB * TT * HH];         // fp32 hs
__device__ float g_henc[BB * HH];
__device__ float g_h0[BB * HH];
__device__ float g_h1[BB * HH];
__device__ bf16  g_hsb[BB * TT * HH];        // bf16 hs (via conv_hs)
__device__ bf16  g_wb[(size_t)VV * HH];      // bf16 out_W ~65 MB
__device__ int   g_is_bf16;
__device__ int   g_tgt64;

// ---------------- dtype-flexible loads -------
__device__ __forceinline__ void ld8_bf16(const bf16* p, float* f) {
    union { uint4 u; __nv_bfloat162 h[4]; } v;
    v.u = *(const uint4*)p;
#pragma unroll
    for (int i = 0; i < 4; i++) {
        float2 t = __bfloat1622float2(v.h[i]);
        f[2 * i] = t.x; f[2 * i + 1] = t.y;
    }
}
__device__ __forceinline__ void ld8_any(const void* base, size_t elem_idx,
                                        float* f, int isbf) {
    if (isbf) {
        ld8_bf16((const bf16*)base + elem_idx, f);
    } else {
        const float4* p = (const float4*)((const float*)base + elem_idx);
        float4 a = p[0], b = p[1];
        f[0] = a.x; f[1] = a.y; f[2] = a.z; f[3] = a.w;
        f[4] = b.x; f[5] = b.y; f[6] = b.z; f[7] = b.w;
    }
}
__device__ __forceinline__ void ld4_any(const void* base, size_t elem_idx,
                                        float* f, int isbf) {
    if (isbf) {
        union { uint2 u; __nv_bfloat162 h[2]; } v;
        v.u = *(const uint2*)((const bf16*)base + elem_idx);
        float2 t0 = __bfloat1622float2(v.h[0]);
        float2 t1 = __bfloat1622float2(v.h[1]);
        f[0] = t0.x; f[1] = t0.y; f[2] = t1.x; f[3] = t1.y;
    } else {
        float4 a = *(const float4*)((const float*)base + elem_idx);
        f[0] = a.x; f[1] = a.y; f[2] = a.z; f[3] = a.w;
    }
}
__device__ __forceinline__ float ld1_any(const void* base, size_t i, int isbf) {
    return isbf ? __bfloat162float(((const bf16*)base)[i]) : ((const float*)base)[i];
}

// =====================================================================
// K-1: dtype detection
// =====================================================================
__global__ void detect_kernel(const void* emb, const int* target)
{
    if (threadIdx.x != 0 || blockIdx.x != 0) return;
    const unsigned short* h = (const unsigned short*)emb;
    int plaus = 0;
    for (int i = 0; i < 512; i++) {
        unsigned short u = h[i];
        int e = (u >> 7) & 0xFF;
        if ((u & 0x7FFF) == 0 || (e >= 112 && e <= 142)) plaus++;
    }
    g_is_bf16 = (plaus >= 410);
    int zeros_odd = 0;
    for (int i = 0; i < 64; i++) if (target[2 * i + 1] == 0) zeros_odd++;
    g_tgt64 = (zeros_odd >= 62);
}

// K0: encoder_hidden -> fp32
__global__ void init_h_kernel(const void* __restrict__ enc_hidden)
{
    int i = blockIdx.x * blockDim.x + threadIdx.x;
    if (i < BB * HH) g_henc[i] = ld1_any(enc_hidden, i, g_is_bf16);
}

// conv: out_W -> bf16  (8 per thread)
__global__ __launch_bounds__(256) void conv_w_kernel(const void* __restrict__ outW)
{
    size_t i = ((size_t)blockIdx.x * 256 + threadIdx.x) * 8;
    if (i >= (size_t)VV * HH) return;
    float f[8];
    ld8_any(outW, i, f, g_is_bf16);
    union { uint4 u; __nv_bfloat162 h[4]; } v;
#pragma unroll
    for (int j = 0; j < 4; j++) v.h[j] = __floats2bfloat162_rn(f[2 * j], f[2 * j + 1]);
    *(uint4*)(g_wb + i) = v.u;
}

// conv: g_hs (fp32) -> g_hsb (bf16)
__global__ __launch_bounds__(256) void conv_hs_kernel()
{
    size_t i = ((size_t)blockIdx.x * 256 + threadIdx.x) * 8;
    if (i >= (size_t)BB * TT * HH) return;
    const float4* p = (const float4*)(g_hs + i);
    float4 a = p[0], b = p[1];
    union { uint4 u; __nv_bfloat162 h[4]; } v;
    v.h[0] = __floats2bfloat162_rn(a.x, a.y);
    v.h[1] = __floats2bfloat162_rn(a.z, a.w);
    v.h[2] = __floats2bfloat162_rn(b.x, b.y);
    v.h[3] = __floats2bfloat162_rn(b.z, b.w);
    *(uint4*)(g_hsb + i) = v.u;
}

// =====================================================================
// K1: gi GEMM — fp32 FFMA (precision-critical: feeds the recurrence).
// =====================================================================
__global__ __launch_bounds__(256) void gi_gemm_kernel(
    const void* __restrict__ emb, const void* __restrict__ Wih,
    const void* __restrict__ bih, const int* __restrict__ target,
    const int* __restrict__ sos)
{
    __shared__ float As[16][128];
    __shared__ float Bs[16][128];
    __shared__ int   toks[128];

    const int tid = threadIdx.x;
    const int isbf = g_is_bf16;
    const int ty = tid >> 4, tx = tid & 15;
    const int rowBase = blockIdx.y * 128;
    const int colBase = blockIdx.x * 128;

    if (tid < 128) {
        int r = rowBase + tid;
        int t = r >> 6;
        int b = r & 63;
        int tok;
        if (t == 0) tok = sos ? sos[0] : 0;
        else {
            int idx = b * TT + (t - 1);
            tok = g_tgt64 ? target[2 * idx] : target[idx];
        }
        toks[tid] = min(max(tok, 0), VV - 1);
    }
    __syncthreads();

    float acc[8][8];
#pragma unroll
    for (int i = 0; i < 8; i++)
#pragma unroll
        for (int j = 0; j < 8; j++) acc[i][j] = 0.f;

    const int lm = tid >> 1;
    const int lk = (tid & 1) * 8;

    for (int kt = 0; kt < HH / 16; kt++) {
        {
            float f[8];
            ld8_any(emb, (size_t)toks[lm] * HH + kt * 16 + lk, f, isbf);
#pragma unroll
            for (int i = 0; i < 8; i++) As[lk + i][lm] = fmaxf(f[i], 0.f);
        }
        {
            float f[8];
            ld8_any(Wih, (size_t)(colBase + lm) * HH + kt * 16 + lk, f, isbf);
#pragma unroll
            for (int i = 0; i < 8; i++) Bs[lk + i][lm] = f[i];
        }
        __syncthreads();
#pragma unroll
        for (int k = 0; k < 16; k++) {
            float a[8], b[8];
            *(float4*)(a)     = *(const float4*)&As[k][ty * 8];
            *(float4*)(a + 4) = *(const float4*)&As[k][ty * 8 + 4];
            *(float4*)(b)     = *(const float4*)&Bs[k][tx * 8];
            *(float4*)(b + 4) = *(const float4*)&Bs[k][tx * 8 + 4];
#pragma unroll
            for (int i = 0; i < 8; i++)
#pragma unroll
                for (int j = 0; j < 8; j++) acc[i][j] = fmaf(a[i], b[j], acc[i][j]);
        }
        __syncthreads();
    }

#pragma unroll
    for (int i = 0; i < 8; i++) {
        int r = rowBase + ty * 8 + i;
#pragma unroll
        for (int j = 0; j < 8; j++) {
            int g = colBase + tx * 8 + j;
            g_gi[(size_t)r * GG + g] = acc[i][j] + ld1_any(bih, g, isbf);
        }
    }
}

// =====================================================================
// K2: GRU step. grid = HH/8 = 128 blocks, 512 threads, K-split-2.
// Writes fp32 g_hs only (bf16 conversion via conv_hs, as in the pass).
// =====================================================================
__global__ __launch_bounds__(512) void gru_step_v3(
    const void* __restrict__ Whh, const void* __restrict__ bhh, int t)
{
    const float* h_in  = (t == 0) ? g_henc : ((t & 1) ? g_h0 : g_h1);
    float*       h_out = (t & 1) ? g_h1 : g_h0;

    __shared__ float h_s[2][16][66];
    __shared__ float w_s[2][3][16][9];
    __shared__ float red[3][8][66];

    const int tid = threadIdx.x;
    const int isbf = g_is_bf16;
    const int half = tid >> 8;
    const int t2 = tid & 255;
    const int jj = t2 & 7;
    const int b0 = (t2 >> 3) * 2;
    const int j0 = blockIdx.x * 8;

    float accr[2] = {0,0}, accz[2] = {0,0}, accn[2] = {0,0};

    const int hb  = t2 & 63;
    const int hk4 = (t2 >> 6) * 4;

    for (int c8 = 0; c8 < 32; c8++) {
        const int kt = half * 32 + c8;
        {
            float4 v = *(const float4*)(h_in + (size_t)hb * HH + kt * 16 + hk4);
            h_s[half][hk4 + 0][hb] = v.x; h_s[half][hk4 + 1][hb] = v.y;
            h_s[half][hk4 + 2][hb] = v.z; h_s[half][hk4 + 3][hb] = v.w;
        }
        if (t2 < 96) {
            int gt = t2 >> 5;
            int rem = t2 & 31;
            int j = rem >> 2;
            int k4 = (rem & 3) * 4;
            float f[4];
            ld4_any(Whh, (size_t)(gt * HH + j0 + j) * HH + kt * 16 + k4, f, isbf);
#pragma unroll
            for (int i = 0; i < 4; i++) w_s[half][gt][k4 + i][j] = f[i];
        }
        __syncthreads();
#pragma unroll
        for (int k = 0; k < 16; k++) {
            float wr = w_s[half][0][k][jj], wz = w_s[half][1][k][jj], wn = w_s[half][2][k][jj];
            float2 hv = *(const float2*)&h_s[half][k][b0];
            accr[0] = fmaf(hv.x, wr, accr[0]); accr[1] = fmaf(hv.y, wr, accr[1]);
            accz[0] = fmaf(hv.x, wz, accz[0]); accz[1] = fmaf(hv.y, wz, accz[1]);
            accn[0] = fmaf(hv.x, wn, accn[0]); accn[1] = fmaf(hv.y, wn, accn[1]);
        }
        __syncthreads();
    }

    if (half == 1) {
#pragma unroll
        for (int i = 0; i < 2; i++) {
            red[0][jj][b0 + i] = accr[i];
            red[1][jj][b0 + i] = accz[i];
            red[2][jj][b0 + i] = accn[i];
        }
    }
    __syncthreads();
    if (half == 0) {
        const int jg = j0 + jj;
        const float br = ld1_any(bhh, jg, isbf);
        const float bz = ld1_any(bhh, HH + jg, isbf);
        const float bn = ld1_any(bhh, 2 * HH + jg, isbf);
#pragma unroll
        for (int i = 0; i < 2; i++) {
            int b = b0 + i;
            const float* girow = g_gi + ((size_t)(t * BB + b)) * GG;
            float ir = girow[jg], iz = girow[HH + jg], inn = girow[2 * HH + jg];
            float ghr = accr[i] + red[0][jj][b] + br;
            float ghz = accz[i] + red[1][jj][b] + bz;
            float ghn = accn[i] + red[2][jj][b] + bn;
            float rg = 1.f / (1.f + expf(-(ir + ghr)));
            float zg = 1.f / (1.f + expf(-(iz + ghz)));
            float ng = tanhf(inn + rg * ghn);
            float hprev = h_in[(size_t)b * HH + jg];
            float hnew = (1.f - zg) * ng + zg * hprev;
            h_out[(size_t)b * HH + jg] = hnew;
            g_hs[((size_t)b * TT + t) * HH + jg] = hnew;
        }
    }
}

// =====================================================================
// K3: projection via bf16 mma.sync -> d_out. Single smem buffer + two
// barriers per k-iter (round-10 proven semantics); global loads hoisted
// one iteration early into registers to hide LDG latency.
// =====================================================================
__global__ __launch_bounds__(256) void out_mma_kernel(
    const void* __restrict__ outb, float* __restrict__ out)
{
    __shared__ __align__(16) bf16 As[128][40];
    __shared__ __align__(16) bf16 Bs[128][40];

    const int tid = threadIdx.x;
    const int warp = tid >> 5, lane = tid & 31;
    const int g = lane >> 2, tg = lane & 3;
    const int m0 = (warp >> 2) * 64;
    const int n0 = (warp & 3) * 32;
    const int rowBase = blockIdx.y * 128;
    const int colBase = blockIdx.x * 128;

    const int lr0 = tid >> 2,           lk0 = (tid & 3) * 8;
    const int lr1 = (tid + 256) >> 2,   lk1 = ((tid + 256) & 3) * 8;

    float acc[4][4][4];
#pragma unroll
    for (int mt = 0; mt < 4; mt++)
#pragma unroll
        for (int nt = 0; nt < 4; nt++)
#pragma unroll
            for (int i = 0; i < 4; i++) acc[mt][nt][i] = 0.f;

    // preload k-tile 0 into registers
    uint4 av0 = *(const uint4*)(g_hsb + (size_t)(rowBase + lr0) * HH + lk0);
    uint4 av1 = *(const uint4*)(g_hsb + (size_t)(rowBase + lr1) * HH + lk1);
    uint4 bv0 = *(const uint4*)(g_wb + (size_t)(colBase + lr0) * HH + lk0);
    uint4 bv1 = *(const uint4*)(g_wb + (size_t)(colBase + lr1) * HH + lk1);

    for (int kt = 0; kt < 32; kt++) {
        // store current tile's registers to smem
        *(uint4*)&As[lr0][lk0] = av0; *(uint4*)&As[lr1][lk1] = av1;
        *(uint4*)&Bs[lr0][lk0] = bv0; *(uint4*)&Bs[lr1][lk1] = bv1;
        __syncthreads();
        // issue next tile's loads (latency hidden behind MMA phase)
        if (kt < 31) {
            const int ko = (kt + 1) * 32;
            av0 = *(const uint4*)(g_hsb + (size_t)(rowBase + lr0) * HH + ko + lk0);
            av1 = *(const uint4*)(g_hsb + (size_t)(rowBase + lr1) * HH + ko + lk1);
            bv0 = *(const uint4*)(g_wb + (size_t)(colBase + lr0) * HH + ko + lk0);
            bv1 = *(const uint4*)(g_wb + (size_t)(colBase + lr1) * HH + ko + lk1);
        }
#pragma unroll
        for (int kk = 0; kk < 32; kk += 16) {
            uint32_t a[4][4], b[4][2];
#pragma unroll
            for (int mt = 0; mt < 4; mt++) {
                a[mt][0] = *(const uint32_t*)&As[m0 + mt * 16 + g][kk + tg * 2];
                a[mt][1] = *(const uint32_t*)&As[m0 + mt * 16 + g + 8][kk + tg * 2];
                a[mt][2] = *(const uint32_t*)&As[m0 + mt * 16 + g][kk + tg * 2 + 8];
                a[mt][3] = *(const uint32_t*)&As[m0 + mt * 16 + g + 8][kk + tg * 2 + 8];
            }
#pragma unroll
            for (int nt = 0; nt < 4; nt++) {
                b[nt][0] = *(const uint32_t*)&Bs[n0 + nt * 8 + g][kk + tg * 2];
                b[nt][1] = *(const uint32_t*)&Bs[n0 + nt * 8 + g][kk + tg * 2 + 8];
            }
#pragma unroll
            for (int mt = 0; mt < 4; mt++)
#pragma unroll
                for (int nt = 0; nt < 4; nt++)
                    asm volatile(
                        "mma.sync.aligned.m16n8k16.row.col.f32.bf16.bf16.f32 "
                        "{%0,%1,%2,%3}, {%4,%5,%6,%7}, {%8,%9}, {%0,%1,%2,%3};"
                        : "+f"(acc[mt][nt][0]), "+f"(acc[mt][nt][1]),
                          "+f"(acc[mt][nt][2]), "+f"(acc[mt][nt][3])
                        : "r"(a[mt][0]), "r"(a[mt][1]), "r"(a[mt][2]), "r"(a[mt][3]),
                          "r"(b[nt][0]), "r"(b[nt][1]));
        }
        __syncthreads();
    }

    const int isbf = g_is_bf16;
#pragma unroll
    for (int mt = 0; mt < 4; mt++) {
#pragma unroll
        for (int nt = 0; nt < 4; nt++) {
            int c = colBase + n0 + nt * 8 + tg * 2;
            float bx = ld1_any(outb, c, isbf);
            float by = ld1_any(outb, c + 1, isbf);
            size_t r0 = rowBase + m0 + mt * 16 + g;
            *(float2*)&out[r0 * VV + c] =
                make_float2(acc[mt][nt][0] + bx, acc[mt][nt][1] + by);
            *(float2*)&out[(r0 + 8) * VV + c] =
                make_float2(acc[mt][nt][2] + bx, acc[mt][nt][3] + by);
        }
    }
}

// =====================================================================
// K4: in-place log_softmax over V on fp32 d_out. 512 thr/row.
// =====================================================================
__global__ __launch_bounds__(512) void logsoftmax_kernel(float* __restrict__ out)
{
    __shared__ float red[512];
    const int tid = threadIdx.x;
    float* p = out + (size_t)blockIdx.x * VV;
    const float4* p4 = (const float4*)p;
    const int n4 = VV / 4;

    float m = -1e30f;
    for (int i = tid; i < n4; i += 512) {
        float4 v = p4[i];
        m = fmaxf(m, fmaxf(fmaxf(v.x, v.y), fmaxf(v.z, v.w)));
    }
    red[tid] = m; __syncthreads();
    for (int s = 256; s > 0; s >>= 1) {
        if (tid < s) red[tid] = fmaxf(red[tid], red[tid + s]);
        __syncthreads();
    }
    m = red[0]; __syncthreads();

    float sum = 0.f;
    for (int i = tid; i < n4; i += 512) {
        float4 v = p4[i];
        sum += expf(v.x - m) + expf(v.y - m) + expf(v.z - m) + expf(v.w - m);
    }
    red[tid] = sum; __syncthreads();
    for (int s = 256; s > 0; s >>= 1) {
        if (tid < s) red[tid] += red[tid + s];
        __syncthreads();
    }
    const float L = m + logf(red[0]);

    float4* w4 = (float4*)p;
    for (int i = tid; i < n4; i += 512) {
        float4 v = w4[i];
        v.x -= L; v.y -= L; v.z -= L; v.w -= L;
        w4[i] = v;
    }
}

// K5: append h_final (t=31 odd -> g_h1), fp32
__global__ void hfinal_kernel(float* __restrict__ out)
{
    int i = blockIdx.x * blockDim.x + threadIdx.x;
    if (i < BB * HH) out[(size_t)BB * TT * VV + i] = g_h1[i];
}

// =====================================================================
extern "C" void kernel_launch(void* const* d_in, const int* in_sizes, int n_in,
                              void* d_out, int out_size)
{
    const void* enc_hidden = nullptr;
    const int*  target     = nullptr;
    const int*  sos        = nullptr;
    const void* emb        = nullptr;
    const void* outW       = nullptr;
    const void* Wih        = nullptr;
    const void* Whh        = nullptr;
    const void* bih        = nullptr;
    const void* bhh        = nullptr;
    const void* outb       = nullptr;

    for (int i = 0; i < n_in; i++) {
        int s = in_sizes[i];
        void* p = d_in[i];
        switch (s) {
            case 65536:     if (!enc_hidden) enc_hidden = p; break;
            case 2048:      target = (const int*)p; break;
            case 1:         if (!sos) sos = (const int*)p; break;
            case 32768000:  if (!emb) emb = p; else outW = p; break;
            case 3145728:   if (!Wih) Wih = p; else Whh = p; break;
            case 3072:      if (!bih) bih = p; else bhh = p; break;
            case 32000:     outb = p; break;
            default: break;
        }
    }
    float* out = (float*)d_out;
    if (!enc_hidden || !target || !emb || !outW || !Wih || !Whh || !bih || !bhh || !outb)
        return;

    detect_kernel<<<1, 32>>>(emb, target);
    init_h_kernel<<<(BB * HH + 255) / 256, 256>>>(enc_hidden);

    // out_W -> bf16 (overlaps with gi/GRU chain in the HW queue)
    conv_w_kernel<<<(int)(((size_t)VV * HH / 8 + 255) / 256), 256>>>(outW);

    // gi GEMM — fp32 FFMA
    {
        dim3 grid(GG / 128, MM / 128);  // 24 x 16
        gi_gemm_kernel<<<grid, 256>>>(emb, Wih, bih, target, sos);
    }

    // 32 sequential GRU steps (writes fp32 g_hs)
    for (int t = 0; t < TT; t++) {
        gru_step_v3<<<HH / 8, 512>>>(Whh, bhh, t);
    }

    // hs -> bf16 (proven path)
    conv_hs_kernel<<<(int)(((size_t)BB * TT * HH / 8 + 255) / 256), 256>>>();

    // projection via tensor cores -> d_out fp32 logits
    {
        dim3 grid(VV / 128, MM / 128);  // 250 x 16
        out_mma_kernel<<<grid, 256>>>(outb, out);
    }

    // in-place log_softmax
    logsoftmax_kernel<<<MM, 512>>>(out);

    if (out_size >= BB * TT * VV + BB * HH) {
        hfinal_kernel<<<(BB * HH + 255) / 256, 256>>>(out);
    }
}

// round 15
// speedup vs baseline: 2.2834x; 1.0172x over previous
#include <cuda_runtime.h>
#include <cuda_bf16.h>
#include <math.h>
#include <stdint.h>

// Problem constants
#define BB 64        // batch
#define TT 32        // max_len
#define HH 1024      // hidden
#define VV 32000     // vocab
#define GG 3072      // 3*H
#define MM 2048      // T*B rows

typedef __nv_bfloat16 bf16;

// ---------------- scratch (static device globals; no allocation) ----------------
__device__ float g_gi[MM * GG];              // [t][b][3H]   ~25 MB
__device__ float g_hs[BB * TT * HH];         // fp32 hs
__device__ float g_henc[BB * HH];
__device__ float g_h0[BB * HH];
__device__ float g_h1[BB * HH];
__device__ bf16  g_hsb[BB * TT * HH];        // bf16 hs (via conv_hs)
__device__ bf16  g_wb[(size_t)VV * HH];      // bf16 out_W ~65 MB
__device__ int   g_is_bf16;
__device__ int   g_tgt64;

// ---------------- dtype-flexible loads -------
__device__ __forceinline__ void ld8_bf16(const bf16* p, float* f) {
    union { uint4 u; __nv_bfloat162 h[4]; } v;
    v.u = *(const uint4*)p;
#pragma unroll
    for (int i = 0; i < 4; i++) {
        float2 t = __bfloat1622float2(v.h[i]);
        f[2 * i] = t.x; f[2 * i + 1] = t.y;
    }
}
__device__ __forceinline__ void ld8_any(const void* base, size_t elem_idx,
                                        float* f, int isbf) {
    if (isbf) {
        ld8_bf16((const bf16*)base + elem_idx, f);
    } else {
        const float4* p = (const float4*)((const float*)base + elem_idx);
        float4 a = p[0], b = p[1];
        f[0] = a.x; f[1] = a.y; f[2] = a.z; f[3] = a.w;
        f[4] = b.x; f[5] = b.y; f[6] = b.z; f[7] = b.w;
    }
}
__device__ __forceinline__ void ld4_any(const void* base, size_t elem_idx,
                                        float* f, int isbf) {
    if (isbf) {
        union { uint2 u; __nv_bfloat162 h[2]; } v;
        v.u = *(const uint2*)((const bf16*)base + elem_idx);
        float2 t0 = __bfloat1622float2(v.h[0]);
        float2 t1 = __bfloat1622float2(v.h[1]);
        f[0] = t0.x; f[1] = t0.y; f[2] = t1.x; f[3] = t1.y;
    } else {
        float4 a = *(const float4*)((const float*)base + elem_idx);
        f[0] = a.x; f[1] = a.y; f[2] = a.z; f[3] = a.w;
    }
}
__device__ __forceinline__ float ld1_any(const void* base, size_t i, int isbf) {
    return isbf ? __bfloat162float(((const bf16*)base)[i]) : ((const float*)base)[i];
}

// =====================================================================
// K-1: dtype detection
// =====================================================================
__global__ void detect_kernel(const void* emb, const int* target)
{
    if (threadIdx.x != 0 || blockIdx.x != 0) return;
    const unsigned short* h = (const unsigned short*)emb;
    int plaus = 0;
    for (int i = 0; i < 512; i++) {
        unsigned short u = h[i];
        int e = (u >> 7) & 0xFF;
        if ((u & 0x7FFF) == 0 || (e >= 112 && e <= 142)) plaus++;
    }
    g_is_bf16 = (plaus >= 410);
    int zeros_odd = 0;
    for (int i = 0; i < 64; i++) if (target[2 * i + 1] == 0) zeros_odd++;
    g_tgt64 = (zeros_odd >= 62);
}

// K0: encoder_hidden -> fp32
__global__ void init_h_kernel(const void* __restrict__ enc_hidden)
{
    int i = blockIdx.x * blockDim.x + threadIdx.x;
    if (i < BB * HH) g_henc[i] = ld1_any(enc_hidden, i, g_is_bf16);
}

// conv: out_W -> bf16  (proven)
__global__ __launch_bounds__(256) void conv_w_kernel(const void* __restrict__ outW)
{
    size_t i = ((size_t)blockIdx.x * 256 + threadIdx.x) * 8;
    if (i >= (size_t)VV * HH) return;
    float f[8];
    ld8_any(outW, i, f, g_is_bf16);
    union { uint4 u; __nv_bfloat162 h[4]; } v;
#pragma unroll
    for (int j = 0; j < 4; j++) v.h[j] = __floats2bfloat162_rn(f[2 * j], f[2 * j + 1]);
    *(uint4*)(g_wb + i) = v.u;
}

// conv: g_hs (fp32) -> g_hsb (bf16)  (proven)
__global__ __launch_bounds__(256) void conv_hs_kernel()
{
    size_t i = ((size_t)blockIdx.x * 256 + threadIdx.x) * 8;
    if (i >= (size_t)BB * TT * HH) return;
    const float4* p = (const float4*)(g_hs + i);
    float4 a = p[0], b = p[1];
    union { uint4 u; __nv_bfloat162 h[4]; } v;
    v.h[0] = __floats2bfloat162_rn(a.x, a.y);
    v.h[1] = __floats2bfloat162_rn(a.z, a.w);
    v.h[2] = __floats2bfloat162_rn(b.x, b.y);
    v.h[3] = __floats2bfloat162_rn(b.z, b.w);
    *(uint4*)(g_hsb + i) = v.u;
}

// =====================================================================
// K1: gi GEMM — fp32 FFMA (precision-critical: feeds the recurrence;
// bf16 here measured 2e-3 on h_final -> fail. Stays fp32.)
// =====================================================================
__global__ __launch_bounds__(256) void gi_gemm_kernel(
    const void* __restrict__ emb, const void* __restrict__ Wih,
    const void* __restrict__ bih, const int* __restrict__ target,
    const int* __restrict__ sos)
{
    __shared__ float As[16][128];
    __shared__ float Bs[16][128];
    __shared__ int   toks[128];

    const int tid = threadIdx.x;
    const int isbf = g_is_bf16;
    const int ty = tid >> 4, tx = tid & 15;
    const int rowBase = blockIdx.y * 128;
    const int colBase = blockIdx.x * 128;

    if (tid < 128) {
        int r = rowBase + tid;
        int t = r >> 6;
        int b = r & 63;
        int tok;
        if (t == 0) tok = sos ? sos[0] : 0;
        else {
            int idx = b * TT + (t - 1);
            tok = g_tgt64 ? target[2 * idx] : target[idx];
        }
        toks[tid] = min(max(tok, 0), VV - 1);
    }
    __syncthreads();

    float acc[8][8];
#pragma unroll
    for (int i = 0; i < 8; i++)
#pragma unroll
        for (int j = 0; j < 8; j++) acc[i][j] = 0.f;

    const int lm = tid >> 1;
    const int lk = (tid & 1) * 8;

    for (int kt = 0; kt < HH / 16; kt++) {
        {
            float f[8];
            ld8_any(emb, (size_t)toks[lm] * HH + kt * 16 + lk, f, isbf);
#pragma unroll
            for (int i = 0; i < 8; i++) As[lk + i][lm] = fmaxf(f[i], 0.f);
        }
        {
            float f[8];
            ld8_any(Wih, (size_t)(colBase + lm) * HH + kt * 16 + lk, f, isbf);
#pragma unroll
            for (int i = 0; i < 8; i++) Bs[lk + i][lm] = f[i];
        }
        __syncthreads();
#pragma unroll
        for (int k = 0; k < 16; k++) {
            float a[8], b[8];
            *(float4*)(a)     = *(const float4*)&As[k][ty * 8];
            *(float4*)(a + 4) = *(const float4*)&As[k][ty * 8 + 4];
            *(float4*)(b)     = *(const float4*)&Bs[k][tx * 8];
            *(float4*)(b + 4) = *(const float4*)&Bs[k][tx * 8 + 4];
#pragma unroll
            for (int i = 0; i < 8; i++)
#pragma unroll
                for (int j = 0; j < 8; j++) acc[i][j] = fmaf(a[i], b[j], acc[i][j]);
        }
        __syncthreads();
    }

#pragma unroll
    for (int i = 0; i < 8; i++) {
        int r = rowBase + ty * 8 + i;
#pragma unroll
        for (int j = 0; j < 8; j++) {
            int g = colBase + tx * 8 + j;
            g_gi[(size_t)r * GG + g] = acc[i][j] + ld1_any(bih, g, isbf);
        }
    }
}

// =====================================================================
// K2: GRU step. grid = HH/8 = 128 blocks, 512 threads, K-split-2. (proven)
// =====================================================================
__global__ __launch_bounds__(512) void gru_step_v3(
    const void* __restrict__ Whh, const void* __restrict__ bhh, int t)
{
    const float* h_in  = (t == 0) ? g_henc : ((t & 1) ? g_h0 : g_h1);
    float*       h_out = (t & 1) ? g_h1 : g_h0;

    __shared__ float h_s[2][16][66];
    __shared__ float w_s[2][3][16][9];
    __shared__ float red[3][8][66];

    const int tid = threadIdx.x;
    const int isbf = g_is_bf16;
    const int half = tid >> 8;
    const int t2 = tid & 255;
    const int jj = t2 & 7;
    const int b0 = (t2 >> 3) * 2;
    const int j0 = blockIdx.x * 8;

    float accr[2] = {0,0}, accz[2] = {0,0}, accn[2] = {0,0};

    const int hb  = t2 & 63;
    const int hk4 = (t2 >> 6) * 4;

    for (int c8 = 0; c8 < 32; c8++) {
        const int kt = half * 32 + c8;
        {
            float4 v = *(const float4*)(h_in + (size_t)hb * HH + kt * 16 + hk4);
            h_s[half][hk4 + 0][hb] = v.x; h_s[half][hk4 + 1][hb] = v.y;
            h_s[half][hk4 + 2][hb] = v.z; h_s[half][hk4 + 3][hb] = v.w;
        }
        if (t2 < 96) {
            int gt = t2 >> 5;
            int rem = t2 & 31;
            int j = rem >> 2;
            int k4 = (rem & 3) * 4;
            float f[4];
            ld4_any(Whh, (size_t)(gt * HH + j0 + j) * HH + kt * 16 + k4, f, isbf);
#pragma unroll
            for (int i = 0; i < 4; i++) w_s[half][gt][k4 + i][j] = f[i];
        }
        __syncthreads();
#pragma unroll
        for (int k = 0; k < 16; k++) {
            float wr = w_s[half][0][k][jj], wz = w_s[half][1][k][jj], wn = w_s[half][2][k][jj];
            float2 hv = *(const float2*)&h_s[half][k][b0];
            accr[0] = fmaf(hv.x, wr, accr[0]); accr[1] = fmaf(hv.y, wr, accr[1]);
            accz[0] = fmaf(hv.x, wz, accz[0]); accz[1] = fmaf(hv.y, wz, accz[1]);
            accn[0] = fmaf(hv.x, wn, accn[0]); accn[1] = fmaf(hv.y, wn, accn[1]);
        }
        __syncthreads();
    }

    if (half == 1) {
#pragma unroll
        for (int i = 0; i < 2; i++) {
            red[0][jj][b0 + i] = accr[i];
            red[1][jj][b0 + i] = accz[i];
            red[2][jj][b0 + i] = accn[i];
        }
    }
    __syncthreads();
    if (half == 0) {
        const int jg = j0 + jj;
        const float br = ld1_any(bhh, jg, isbf);
        const float bz = ld1_any(bhh, HH + jg, isbf);
        const float bn = ld1_any(bhh, 2 * HH + jg, isbf);
#pragma unroll
        for (int i = 0; i < 2; i++) {
            int b = b0 + i;
            const float* girow = g_gi + ((size_t)(t * BB + b)) * GG;
            float ir = girow[jg], iz = girow[HH + jg], inn = girow[2 * HH + jg];
            float ghr = accr[i] + red[0][jj][b] + br;
            float ghz = accz[i] + red[1][jj][b] + bz;
            float ghn = accn[i] + red[2][jj][b] + bn;
            float rg = 1.f / (1.f + expf(-(ir + ghr)));
            float zg = 1.f / (1.f + expf(-(iz + ghz)));
            float ng = tanhf(inn + rg * ghn);
            float hprev = h_in[(size_t)b * HH + jg];
            float hnew = (1.f - zg) * ng + zg * hprev;
            h_out[(size_t)b * HH + jg] = hnew;
            g_hs[((size_t)b * TT + t) * HH + jg] = hnew;
        }
    }
}

// =====================================================================
// K3: projection via bf16 mma.sync -> d_out.
// Same proven single-buffer + hoisted-prefetch structure as R13; the
// ONLY changes: fragment loads via ldmatrix (bit-identical values; the
// m8n8 non-trans result distribution lane(g,tg)->{row g, cols 2tg,2tg+1}
// equals the previous scalar indices), and launch_bounds(256,2) for
// 2 CTAs/SM.
// =====================================================================
#define LDSM_X4(r0, r1, r2, r3, addr) \
    asm volatile("ldmatrix.sync.aligned.m8n8.x4.shared.b16 {%0,%1,%2,%3}, [%4];" \
                 : "=r"(r0), "=r"(r1), "=r"(r2), "=r"(r3) : "r"(addr))
#define LDSM_X2(r0, r1, addr) \
    asm volatile("ldmatrix.sync.aligned.m8n8.x2.shared.b16 {%0,%1}, [%2];" \
                 : "=r"(r0), "=r"(r1) : "r"(addr))

__global__ __launch_bounds__(256, 2) void out_mma_kernel(
    const void* __restrict__ outb, float* __restrict__ out)
{
    __shared__ __align__(16) bf16 As[128][40];   // row stride 80 B (16B-aligned)
    __shared__ __align__(16) bf16 Bs[128][40];

    const int tid = threadIdx.x;
    const int warp = tid >> 5, lane = tid & 31;
    const int g = lane >> 2, tg = lane & 3;
    const int m0 = (warp >> 2) * 64;
    const int n0 = (warp & 3) * 32;
    const int rowBase = blockIdx.y * 128;
    const int colBase = blockIdx.x * 128;

    const int lr0 = tid >> 2,           lk0 = (tid & 3) * 8;
    const int lr1 = (tid + 256) >> 2,   lk1 = ((tid + 256) & 3) * 8;

    // ldmatrix per-lane base addresses (row part; column term added per kk)
    const uint32_t asA = (uint32_t)__cvta_generic_to_shared(&As[0][0]);
    const uint32_t asB = (uint32_t)__cvta_generic_to_shared(&Bs[0][0]);
    // A x4: lanes 0-7 -> rows r+0..7 (k lo), 8-15 -> rows+8 (k lo),
    //       16-23 -> rows (k hi), 24-31 -> rows+8 (k hi)
    const int a_row_in_warp = (lane & 7) + ((lane >> 3) & 1) * 8;
    const uint32_t a_col_off = (uint32_t)((lane >> 4) * 16);   // +8 halfs = 16 B
    uint32_t a_base[4];
#pragma unroll
    for (int mt = 0; mt < 4; mt++)
        a_base[mt] = asA + (uint32_t)(m0 + mt * 16 + a_row_in_warp) * 80u + a_col_off;
    // B x2: lanes 0-7 -> rows (k lo), 8-15 -> rows (k hi); lanes 16+ unused
    const uint32_t b_col_off = (uint32_t)(((lane >> 3) & 1) * 16);
    uint32_t b_base[4];
#pragma unroll
    for (int nt = 0; nt < 4; nt++)
        b_base[nt] = asB + (uint32_t)(n0 + nt * 8 + (lane & 7)) * 80u + b_col_off;

    float acc[4][4][4];
#pragma unroll
    for (int mt = 0; mt < 4; mt++)
#pragma unroll
        for (int nt = 0; nt < 4; nt++)
#pragma unroll
            for (int i = 0; i < 4; i++) acc[mt][nt][i] = 0.f;

    // preload k-tile 0 into registers (proven R13 schedule)
    uint4 av0 = *(const uint4*)(g_hsb + (size_t)(rowBase + lr0) * HH + lk0);
    uint4 av1 = *(const uint4*)(g_hsb + (size_t)(rowBase + lr1) * HH + lk1);
    uint4 bv0 = *(const uint4*)(g_wb + (size_t)(colBase + lr0) * HH + lk0);
    uint4 bv1 = *(const uint4*)(g_wb + (size_t)(colBase + lr1) * HH + lk1);

    for (int kt = 0; kt < 32; kt++) {
        *(uint4*)&As[lr0][lk0] = av0; *(uint4*)&As[lr1][lk1] = av1;
        *(uint4*)&Bs[lr0][lk0] = bv0; *(uint4*)&Bs[lr1][lk1] = bv1;
        __syncthreads();
        if (kt < 31) {
            const int ko = (kt + 1) * 32;
            av0 = *(const uint4*)(g_hsb + (size_t)(rowBase + lr0) * HH + ko + lk0);
            av1 = *(const uint4*)(g_hsb + (size_t)(rowBase + lr1) * HH + ko + lk1);
            bv0 = *(const uint4*)(g_wb + (size_t)(colBase + lr0) * HH + ko + lk0);
            bv1 = *(const uint4*)(g_wb + (size_t)(colBase + lr1) * HH + ko + lk1);
        }
#pragma unroll
        for (int kk = 0; kk < 32; kk += 16) {
            uint32_t a[4][4], b[4][2];
#pragma unroll
            for (int mt = 0; mt < 4; mt++)
                LDSM_X4(a[mt][0], a[mt][1], a[mt][2], a[mt][3],
                        a_base[mt] + (uint32_t)(kk * 2));
#pragma unroll
            for (int nt = 0; nt < 4; nt++)
                LDSM_X2(b[nt][0], b[nt][1], b_base[nt] + (uint32_t)(kk * 2));
#pragma unroll
            for (int mt = 0; mt < 4; mt++)
#pragma unroll
                for (int nt = 0; nt < 4; nt++)
                    asm volatile(
                        "mma.sync.aligned.m16n8k16.row.col.f32.bf16.bf16.f32 "
                        "{%0,%1,%2,%3}, {%4,%5,%6,%7}, {%8,%9}, {%0,%1,%2,%3};"
                        : "+f"(acc[mt][nt][0]), "+f"(acc[mt][nt][1]),
                          "+f"(acc[mt][nt][2]), "+f"(acc[mt][nt][3])
                        : "r"(a[mt][0]), "r"(a[mt][1]), "r"(a[mt][2]), "r"(a[mt][3]),
                          "r"(b[nt][0]), "r"(b[nt][1]));
        }
        __syncthreads();
    }

    const int isbf = g_is_bf16;
#pragma unroll
    for (int mt = 0; mt < 4; mt++) {
#pragma unroll
        for (int nt = 0; nt < 4; nt++) {
            int c = colBase + n0 + nt * 8 + tg * 2;
            float bx = ld1_any(outb, c, isbf);
            float by = ld1_any(outb, c + 1, isbf);
            size_t r0 = rowBase + m0 + mt * 16 + g;
            *(float2*)&out[r0 * VV + c] =
                make_float2(acc[mt][nt][0] + bx, acc[mt][nt][1] + by);
            *(float2*)&out[(r0 + 8) * VV + c] =
                make_float2(acc[mt][nt][2] + bx, acc[mt][nt][3] + by);
        }
    }
}

// =====================================================================
// K4: in-place log_softmax over V on fp32 d_out. 512 thr/row.
// =====================================================================
__global__ __launch_bounds__(512) void logsoftmax_kernel(float* __restrict__ out)
{
    __shared__ float red[512];
    const int tid = threadIdx.x;
    float* p = out + (size_t)blockIdx.x * VV;
    const float4* p4 = (const float4*)p;
    const int n4 = VV / 4;

    float m = -1e30f;
    for (int i = tid; i < n4; i += 512) {
        float4 v = p4[i];
        m = fmaxf(m, fmaxf(fmaxf(v.x, v.y), fmaxf(v.z, v.w)));
    }
    red[tid] = m; __syncthreads();
    for (int s = 256; s > 0; s >>= 1) {
        if (tid < s) red[tid] = fmaxf(red[tid], red[tid + s]);
        __syncthreads();
    }
    m = red[0]; __syncthreads();

    float sum = 0.f;
    for (int i = tid; i < n4; i += 512) {
        float4 v = p4[i];
        sum += expf(v.x - m) + expf(v.y - m) + expf(v.z - m) + expf(v.w - m);
    }
    red[tid] = sum; __syncthreads();
    for (int s = 256; s > 0; s >>= 1) {
        if (tid < s) red[tid] += red[tid + s];
        __syncthreads();
    }
    const float L = m + logf(red[0]);

    float4* w4 = (float4*)p;
    for (int i = tid; i < n4; i += 512) {
        float4 v = w4[i];
        v.x -= L; v.y -= L; v.z -= L; v.w -= L;
        w4[i] = v;
    }
}

// K5: append h_final (t=31 odd -> g_h1), fp32
__global__ void hfinal_kernel(float* __restrict__ out)
{
    int i = blockIdx.x * blockDim.x + threadIdx.x;
    if (i < BB * HH) out[(size_t)BB * TT * VV + i] = g_h1[i];
}

// =====================================================================
extern "C" void kernel_launch(void* const* d_in, const int* in_sizes, int n_in,
                              void* d_out, int out_size)
{
    const void* enc_hidden = nullptr;
    const int*  target     = nullptr;
    const int*  sos        = nullptr;
    const void* emb        = nullptr;
    const void* outW       = nullptr;
    const void* Wih        = nullptr;
    const void* Whh        = nullptr;
    const void* bih        = nullptr;
    const void* bhh        = nullptr;
    const void* outb       = nullptr;

    for (int i = 0; i < n_in; i++) {
        int s = in_sizes[i];
        void* p = d_in[i];
        switch (s) {
            case 65536:     if (!enc_hidden) enc_hidden = p; break;
            case 2048:      target = (const int*)p; break;
            case 1:         if (!sos) sos = (const int*)p; break;
            case 32768000:  if (!emb) emb = p; else outW = p; break;
            case 3145728:   if (!Wih) Wih = p; else Whh = p; break;
            case 3072:      if (!bih) bih = p; else bhh = p; break;
            case 32000:     outb = p; break;
            default: break;
        }
    }
    float* out = (float*)d_out;
    if (!enc_hidden || !target || !emb || !outW || !Wih || !Whh || !bih || !bhh || !outb)
        return;

    detect_kernel<<<1, 32>>>(emb, target);
    init_h_kernel<<<(BB * HH + 255) / 256, 256>>>(enc_hidden);

    // out_W -> bf16 (overlaps with gi/GRU chain in the HW queue)
    conv_w_kernel<<<(int)(((size_t)VV * HH / 8 + 255) / 256), 256>>>(outW);

    // gi GEMM — fp32 FFMA
    {
        dim3 grid(GG / 128, MM / 128);  // 24 x 16
        gi_gemm_kernel<<<grid, 256>>>(emb, Wih, bih, target, sos);
    }

    // 32 sequential GRU steps (writes fp32 g_hs)
    for (int t = 0; t < TT; t++) {
        gru_step_v3<<<HH / 8, 512>>>(Whh, bhh, t);
    }

    // hs -> bf16 (proven path)
    conv_hs_kernel<<<(int)(((size_t)BB * TT * HH / 8 + 255) / 256), 256>>>();

    // projection via tensor cores -> d_out fp32 logits
    {
        dim3 grid(VV / 128, MM / 128);  // 250 x 16
        out_mma_kernel<<<grid, 256>>>(outb, out);
    }

    // in-place log_softmax
    logsoftmax_kernel<<<MM, 512>>>(out);

    if (out_size >= BB * TT * VV + BB * HH) {
        hfinal_kernel<<<(BB * HH + 255) / 256, 256>>>(out);
    }
}

// round 17
// speedup vs baseline: 2.5301x; 1.1080x over previous
#include <cuda_runtime.h>
#include <cuda_bf16.h>
#include <math.h>
#include <stdint.h>

// Problem constants
#define BB 64        // batch
#define TT 32        // max_len
#define HH 1024      // hidden
#define VV 32000     // vocab
#define GG 3072      // 3*H
#define MM 2048      // T*B rows

typedef __nv_bfloat16 bf16;

// ---------------- scratch (static device globals; no allocation) ----------------
__device__ float g_gi[MM * GG];              // [t][b][3H]   ~25 MB
__device__ float g_hs[BB * TT * HH];         // fp32 hs
__device__ float g_henc[BB * HH];
__device__ float g_h0[BB * HH];
__device__ float g_h1[BB * HH];
__device__ float g_xf[MM * HH];              // fp32 relu(emb[tok]) rows ~8 MB
__device__ bf16  g_hsb[BB * TT * HH];        // bf16 hs (via conv_hs)
__device__ bf16  g_wb[(size_t)VV * HH];      // bf16 out_W ~65 MB
__device__ int   g_is_bf16;
__device__ int   g_tgt64;

// ---------------- dtype-flexible loads -------
__device__ __forceinline__ void ld8_bf16(const bf16* p, float* f) {
    union { uint4 u; __nv_bfloat162 h[4]; } v;
    v.u = *(const uint4*)p;
#pragma unroll
    for (int i = 0; i < 4; i++) {
        float2 t = __bfloat1622float2(v.h[i]);
        f[2 * i] = t.x; f[2 * i + 1] = t.y;
    }
}
__device__ __forceinline__ void ld8_any(const void* base, size_t elem_idx,
                                        float* f, int isbf) {
    if (isbf) {
        ld8_bf16((const bf16*)base + elem_idx, f);
    } else {
        const float4* p = (const float4*)((const float*)base + elem_idx);
        float4 a = p[0], b = p[1];
        f[0] = a.x; f[1] = a.y; f[2] = a.z; f[3] = a.w;
        f[4] = b.x; f[5] = b.y; f[6] = b.z; f[7] = b.w;
    }
}
__device__ __forceinline__ void ld4_any(const void* base, size_t elem_idx,
                                        float* f, int isbf) {
    if (isbf) {
        union { uint2 u; __nv_bfloat162 h[2]; } v;
        v.u = *(const uint2*)((const bf16*)base + elem_idx);
        float2 t0 = __bfloat1622float2(v.h[0]);
        float2 t1 = __bfloat1622float2(v.h[1]);
        f[0] = t0.x; f[1] = t0.y; f[2] = t1.x; f[3] = t1.y;
    } else {
        float4 a = *(const float4*)((const float*)base + elem_idx);
        f[0] = a.x; f[1] = a.y; f[2] = a.z; f[3] = a.w;
    }
}
__device__ __forceinline__ float ld1_any(const void* base, size_t i, int isbf) {
    return isbf ? __bfloat162float(((const bf16*)base)[i]) : ((const float*)base)[i];
}
__device__ __forceinline__ uint32_t f2tf32(float x) {
    uint32_t r;
    asm("cvt.rna.tf32.f32 %0, %1;" : "=r"(r) : "f"(x));
    return r;
}

// =====================================================================
// K-1: dtype detection
// =====================================================================
__global__ void detect_kernel(const void* emb, const int* target)
{
    if (threadIdx.x != 0 || blockIdx.x != 0) return;
    const unsigned short* h = (const unsigned short*)emb;
    int plaus = 0;
    for (int i = 0; i < 512; i++) {
        unsigned short u = h[i];
        int e = (u >> 7) & 0xFF;
        if ((u & 0x7FFF) == 0 || (e >= 112 && e <= 142)) plaus++;
    }
    g_is_bf16 = (plaus >= 410);
    int zeros_odd = 0;
    for (int i = 0; i < 64; i++) if (target[2 * i + 1] == 0) zeros_odd++;
    g_tgt64 = (zeros_odd >= 62);
}

// K0: encoder_hidden -> fp32
__global__ void init_h_kernel(const void* __restrict__ enc_hidden)
{
    int i = blockIdx.x * blockDim.x + threadIdx.x;
    if (i < BB * HH) g_henc[i] = ld1_any(enc_hidden, i, g_is_bf16);
}

// conv: out_W -> bf16  (proven)
__global__ __launch_bounds__(256) void conv_w_kernel(const void* __restrict__ outW)
{
    size_t i = ((size_t)blockIdx.x * 256 + threadIdx.x) * 8;
    if (i >= (size_t)VV * HH) return;
    float f[8];
    ld8_any(outW, i, f, g_is_bf16);
    union { uint4 u; __nv_bfloat162 h[4]; } v;
#pragma unroll
    for (int j = 0; j < 4; j++) v.h[j] = __floats2bfloat162_rn(f[2 * j], f[2 * j + 1]);
    *(uint4*)(g_wb + i) = v.u;
}

// build x rows fp32: g_xf[r*HH+h] = relu(emb[tok(r)][h])
__global__ __launch_bounds__(256) void build_xf_kernel(
    const void* __restrict__ emb, const int* __restrict__ target,
    const int* __restrict__ sos)
{
    size_t i = ((size_t)blockIdx.x * 256 + threadIdx.x) * 8;
    if (i >= (size_t)MM * HH) return;
    int r = (int)(i / HH);
    int h = (int)(i % HH);
    int t = r >> 6, b = r & 63;
    int tok;
    if (t == 0) tok = sos ? sos[0] : 0;
    else {
        int idx = b * TT + (t - 1);
        tok = g_tgt64 ? target[2 * idx] : target[idx];
    }
    tok = min(max(tok, 0), VV - 1);
    float f[8];
    ld8_any(emb, (size_t)tok * HH + h, f, g_is_bf16);
    float4 lo = make_float4(fmaxf(f[0],0.f), fmaxf(f[1],0.f), fmaxf(f[2],0.f), fmaxf(f[3],0.f));
    float4 hi = make_float4(fmaxf(f[4],0.f), fmaxf(f[5],0.f), fmaxf(f[6],0.f), fmaxf(f[7],0.f));
    *(float4*)(g_xf + i) = lo;
    *(float4*)(g_xf + i + 4) = hi;
}

// conv: g_hs (fp32) -> g_hsb (bf16)  (proven)
__global__ __launch_bounds__(256) void conv_hs_kernel()
{
    size_t i = ((size_t)blockIdx.x * 256 + threadIdx.x) * 8;
    if (i >= (size_t)BB * TT * HH) return;
    const float4* p = (const float4*)(g_hs + i);
    float4 a = p[0], b = p[1];
    union { uint4 u; __nv_bfloat162 h[4]; } v;
    v.h[0] = __floats2bfloat162_rn(a.x, a.y);
    v.h[1] = __floats2bfloat162_rn(a.z, a.w);
    v.h[2] = __floats2bfloat162_rn(b.x, b.y);
    v.h[3] = __floats2bfloat162_rn(b.z, b.w);
    *(uint4*)(g_hsb + i) = v.u;
}

// =====================================================================
// K1: gi GEMM via tf32 mma (m16n8k8). A=g_xf [2048,1024] fp32,
// B=W_ih [3072,1024] (input dtype), C=g_gi fp32 + bias.
// Proven 128x128 tile shape, 8 warps (2m x 4n), k-chunk 32, single
// smem buffer, 2 CTAs/SM.
// =====================================================================
__global__ __launch_bounds__(256, 2) void gi_tf32_kernel(
    const void* __restrict__ Wih, const void* __restrict__ bih)
{
    __shared__ __align__(16) uint32_t As[128][36];  // tf32 bits, pad 4
    __shared__ __align__(16) uint32_t Bs[128][36];

    const int tid = threadIdx.x;
    const int isbf = g_is_bf16;
    const int warp = tid >> 5, lane = tid & 31;
    const int g = lane >> 2, tg = lane & 3;
    const int m0 = (warp >> 2) * 64;
    const int n0 = (warp & 3) * 32;
    const int rowBase = blockIdx.y * 128;
    const int colBase = blockIdx.x * 128;

    // loaders: 256 threads; each thread: row = tid>>1, 16 floats at (tid&1)*16
    const int lr = tid >> 1;
    const int lk = (tid & 1) * 16;

    float acc[4][4][4];
#pragma unroll
    for (int mt = 0; mt < 4; mt++)
#pragma unroll
        for (int nt = 0; nt < 4; nt++)
#pragma unroll
            for (int i = 0; i < 4; i++) acc[mt][nt][i] = 0.f;

    for (int kt = 0; kt < 32; kt++) {
        const int ko = kt * 32;
        {
            const float4* pa = (const float4*)(g_xf + (size_t)(rowBase + lr) * HH + ko + lk);
#pragma unroll
            for (int q = 0; q < 4; q++) {
                float4 v = pa[q];
                As[lr][lk + q * 4 + 0] = f2tf32(v.x);
                As[lr][lk + q * 4 + 1] = f2tf32(v.y);
                As[lr][lk + q * 4 + 2] = f2tf32(v.z);
                As[lr][lk + q * 4 + 3] = f2tf32(v.w);
            }
            float fb[16];
            ld8_any(Wih, (size_t)(colBase + lr) * HH + ko + lk, fb, isbf);
            ld8_any(Wih, (size_t)(colBase + lr) * HH + ko + lk + 8, fb + 8, isbf);
#pragma unroll
            for (int q = 0; q < 16; q++) Bs[lr][lk + q] = f2tf32(fb[q]);
        }
        __syncthreads();
#pragma unroll
        for (int kk = 0; kk < 32; kk += 8) {
            uint32_t a[4][4], b[4][2];
#pragma unroll
            for (int mt = 0; mt < 4; mt++) {
                a[mt][0] = As[m0 + mt * 16 + g][kk + tg];
                a[mt][1] = As[m0 + mt * 16 + g + 8][kk + tg];
                a[mt][2] = As[m0 + mt * 16 + g][kk + tg + 4];
                a[mt][3] = As[m0 + mt * 16 + g + 8][kk + tg + 4];
            }
#pragma unroll
            for (int nt = 0; nt < 4; nt++) {
                b[nt][0] = Bs[n0 + nt * 8 + g][kk + tg];
                b[nt][1] = Bs[n0 + nt * 8 + g][kk + tg + 4];
            }
#pragma unroll
            for (int mt = 0; mt < 4; mt++)
#pragma unroll
                for (int nt = 0; nt < 4; nt++)
                    asm volatile(
                        "mma.sync.aligned.m16n8k8.row.col.f32.tf32.tf32.f32 "
                        "{%0,%1,%2,%3}, {%4,%5,%6,%7}, {%8,%9}, {%0,%1,%2,%3};"
                        : "+f"(acc[mt][nt][0]), "+f"(acc[mt][nt][1]),
                          "+f"(acc[mt][nt][2]), "+f"(acc[mt][nt][3])
                        : "r"(a[mt][0]), "r"(a[mt][1]), "r"(a[mt][2]), "r"(a[mt][3]),
                          "r"(b[nt][0]), "r"(b[nt][1]));
        }
        __syncthreads();
    }

#pragma unroll
    for (int mt = 0; mt < 4; mt++) {
#pragma unroll
        for (int nt = 0; nt < 4; nt++) {
            int c = colBase + n0 + nt * 8 + tg * 2;
            float bx = ld1_any(bih, c, isbf);
            float by = ld1_any(bih, c + 1, isbf);
            size_t r0 = rowBase + m0 + mt * 16 + g;
            *(float2*)&g_gi[r0 * GG + c] =
                make_float2(acc[mt][nt][0] + bx, acc[mt][nt][1] + by);
            *(float2*)&g_gi[(r0 + 8) * GG + c] =
                make_float2(acc[mt][nt][2] + bx, acc[mt][nt][3] + by);
        }
    }
}

// =====================================================================
// K2: GRU step. grid = HH/8 = 128 blocks, 512 threads, K-split-2. (proven)
// =====================================================================
__global__ __launch_bounds__(512) void gru_step_v3(
    const void* __restrict__ Whh, const void* __restrict__ bhh, int t)
{
    const float* h_in  = (t == 0) ? g_henc : ((t & 1) ? g_h0 : g_h1);
    float*       h_out = (t & 1) ? g_h1 : g_h0;

    __shared__ float h_s[2][16][66];
    __shared__ float w_s[2][3][16][9];
    __shared__ float red[3][8][66];

    const int tid = threadIdx.x;
    const int isbf = g_is_bf16;
    const int half = tid >> 8;
    const int t2 = tid & 255;
    const int jj = t2 & 7;
    const int b0 = (t2 >> 3) * 2;
    const int j0 = blockIdx.x * 8;

    float accr[2] = {0,0}, accz[2] = {0,0}, accn[2] = {0,0};

    const int hb  = t2 & 63;
    const int hk4 = (t2 >> 6) * 4;

    for (int c8 = 0; c8 < 32; c8++) {
        const int kt = half * 32 + c8;
        {
            float4 v = *(const float4*)(h_in + (size_t)hb * HH + kt * 16 + hk4);
            h_s[half][hk4 + 0][hb] = v.x; h_s[half][hk4 + 1][hb] = v.y;
            h_s[half][hk4 + 2][hb] = v.z; h_s[half][hk4 + 3][hb] = v.w;
        }
        if (t2 < 96) {
            int gt = t2 >> 5;
            int rem = t2 & 31;
            int j = rem >> 2;
            int k4 = (rem & 3) * 4;
            float f[4];
            ld4_any(Whh, (size_t)(gt * HH + j0 + j) * HH + kt * 16 + k4, f, isbf);
#pragma unroll
            for (int i = 0; i < 4; i++) w_s[half][gt][k4 + i][j] = f[i];
        }
        __syncthreads();
#pragma unroll
        for (int k = 0; k < 16; k++) {
            float wr = w_s[half][0][k][jj], wz = w_s[half][1][k][jj], wn = w_s[half][2][k][jj];
            float2 hv = *(const float2*)&h_s[half][k][b0];
            accr[0] = fmaf(hv.x, wr, accr[0]); accr[1] = fmaf(hv.y, wr, accr[1]);
            accz[0] = fmaf(hv.x, wz, accz[0]); accz[1] = fmaf(hv.y, wz, accz[1]);
            accn[0] = fmaf(hv.x, wn, accn[0]); accn[1] = fmaf(hv.y, wn, accn[1]);
        }
        __syncthreads();
    }

    if (half == 1) {
#pragma unroll
        for (int i = 0; i < 2; i++) {
            red[0][jj][b0 + i] = accr[i];
            red[1][jj][b0 + i] = accz[i];
            red[2][jj][b0 + i] = accn[i];
        }
    }
    __syncthreads();
    if (half == 0) {
        const int jg = j0 + jj;
        const float br = ld1_any(bhh, jg, isbf);
        const float bz = ld1_any(bhh, HH + jg, isbf);
        const float bn = ld1_any(bhh, 2 * HH + jg, isbf);
#pragma unroll
        for (int i = 0; i < 2; i++) {
            int b = b0 + i;
            const float* girow = g_gi + ((size_t)(t * BB + b)) * GG;
            float ir = girow[jg], iz = girow[HH + jg], inn = girow[2 * HH + jg];
            float ghr = accr[i] + red[0][jj][b] + br;
            float ghz = accz[i] + red[1][jj][b] + bz;
            float ghn = accn[i] + red[2][jj][b] + bn;
            float rg = 1.f / (1.f + expf(-(ir + ghr)));
            float zg = 1.f / (1.f + expf(-(iz + ghz)));
            float ng = tanhf(inn + rg * ghn);
            float hprev = h_in[(size_t)b * HH + jg];
            float hnew = (1.f - zg) * ng + zg * hprev;
            h_out[(size_t)b * HH + jg] = hnew;
            g_hs[((size_t)b * TT + t) * HH + jg] = hnew;
        }
    }
}

// =====================================================================
// K3: projection via bf16 mma.sync + ldmatrix -> d_out (proven R15, untouched)
// =====================================================================
#define LDSM_X4(r0, r1, r2, r3, addr) \
    asm volatile("ldmatrix.sync.aligned.m8n8.x4.shared.b16 {%0,%1,%2,%3}, [%4];" \
                 : "=r"(r0), "=r"(r1), "=r"(r2), "=r"(r3) : "r"(addr))
#define LDSM_X2(r0, r1, addr) \
    asm volatile("ldmatrix.sync.aligned.m8n8.x2.shared.b16 {%0,%1}, [%2];" \
                 : "=r"(r0), "=r"(r1) : "r"(addr))

__global__ __launch_bounds__(256, 2) void out_mma_kernel(
    const void* __restrict__ outb, float* __restrict__ out)
{
    __shared__ __align__(16) bf16 As[128][40];
    __shared__ __align__(16) bf16 Bs[128][40];

    const int tid = threadIdx.x;
    const int warp = tid >> 5, lane = tid & 31;
    const int g = lane >> 2, tg = lane & 3;
    const int m0 = (warp >> 2) * 64;
    const int n0 = (warp & 3) * 32;
    const int rowBase = blockIdx.y * 128;
    const int colBase = blockIdx.x * 128;

    const int lr0 = tid >> 2,           lk0 = (tid & 3) * 8;
    const int lr1 = (tid + 256) >> 2,   lk1 = ((tid + 256) & 3) * 8;

    const uint32_t asA = (uint32_t)__cvta_generic_to_shared(&As[0][0]);
    const uint32_t asB = (uint32_t)__cvta_generic_to_shared(&Bs[0][0]);
    const int a_row_in_warp = (lane & 7) + ((lane >> 3) & 1) * 8;
    const uint32_t a_col_off = (uint32_t)((lane >> 4) * 16);
    uint32_t a_base[4];
#pragma unroll
    for (int mt = 0; mt < 4; mt++)
        a_base[mt] = asA + (uint32_t)(m0 + mt * 16 + a_row_in_warp) * 80u + a_col_off;
    const uint32_t b_col_off = (uint32_t)(((lane >> 3) & 1) * 16);
    uint32_t b_base[4];
#pragma unroll
    for (int nt = 0; nt < 4; nt++)
        b_base[nt] = asB + (uint32_t)(n0 + nt * 8 + (lane & 7)) * 80u + b_col_off;

    float acc[4][4][4];
#pragma unroll
    for (int mt = 0; mt < 4; mt++)
#pragma unroll
        for (int nt = 0; nt < 4; nt++)
#pragma unroll
            for (int i = 0; i < 4; i++) acc[mt][nt][i] = 0.f;

    uint4 av0 = *(const uint4*)(g_hsb + (size_t)(rowBase + lr0) * HH + lk0);
    uint4 av1 = *(const uint4*)(g_hsb + (size_t)(rowBase + lr1) * HH + lk1);
    uint4 bv0 = *(const uint4*)(g_wb + (size_t)(colBase + lr0) * HH + lk0);
    uint4 bv1 = *(const uint4*)(g_wb + (size_t)(colBase + lr1) * HH + lk1);

    for (int kt = 0; kt < 32; kt++) {
        *(uint4*)&As[lr0][lk0] = av0; *(uint4*)&As[lr1][lk1] = av1;
        *(uint4*)&Bs[lr0][lk0] = bv0; *(uint4*)&Bs[lr1][lk1] = bv1;
        __syncthreads();
        if (kt < 31) {
            const int ko = (kt + 1) * 32;
            av0 = *(const uint4*)(g_hsb + (size_t)(rowBase + lr0) * HH + ko + lk0);
            av1 = *(const uint4*)(g_hsb + (size_t)(rowBase + lr1) * HH + ko + lk1);
            bv0 = *(const uint4*)(g_wb + (size_t)(colBase + lr0) * HH + ko + lk0);
            bv1 = *(const uint4*)(g_wb + (size_t)(colBase + lr1) * HH + ko + lk1);
        }
#pragma unroll
        for (int kk = 0; kk < 32; kk += 16) {
            uint32_t a[4][4], b[4][2];
#pragma unroll
            for (int mt = 0; mt < 4; mt++)
                LDSM_X4(a[mt][0], a[mt][1], a[mt][2], a[mt][3],
                        a_base[mt] + (uint32_t)(kk * 2));
#pragma unroll
            for (int nt = 0; nt < 4; nt++)
                LDSM_X2(b[nt][0], b[nt][1], b_base[nt] + (uint32_t)(kk * 2));
#pragma unroll
            for (int mt = 0; mt < 4; mt++)
#pragma unroll
                for (int nt = 0; nt < 4; nt++)
                    asm volatile(
                        "mma.sync.aligned.m16n8k16.row.col.f32.bf16.bf16.f32 "
                        "{%0,%1,%2,%3}, {%4,%5,%6,%7}, {%8,%9}, {%0,%1,%2,%3};"
                        : "+f"(acc[mt][nt][0]), "+f"(acc[mt][nt][1]),
                          "+f"(acc[mt][nt][2]), "+f"(acc[mt][nt][3])
                        : "r"(a[mt][0]), "r"(a[mt][1]), "r"(a[mt][2]), "r"(a[mt][3]),
                          "r"(b[nt][0]), "r"(b[nt][1]));
        }
        __syncthreads();
    }

    const int isbf = g_is_bf16;
#pragma unroll
    for (int mt = 0; mt < 4; mt++) {
#pragma unroll
        for (int nt = 0; nt < 4; nt++) {
            int c = colBase + n0 + nt * 8 + tg * 2;
            float bx = ld1_any(outb, c, isbf);
            float by = ld1_any(outb, c + 1, isbf);
            size_t r0 = rowBase + m0 + mt * 16 + g;
            *(float2*)&out[r0 * VV + c] =
                make_float2(acc[mt][nt][0] + bx, acc[mt][nt][1] + by);
            *(float2*)&out[(r0 + 8) * VV + c] =
                make_float2(acc[mt][nt][2] + bx, acc[mt][nt][3] + by);
        }
    }
}

// =====================================================================
// K4: in-place log_softmax over V on fp32 d_out. 512 thr/row.
// =====================================================================
__global__ __launch_bounds__(512) void logsoftmax_kernel(float* __restrict__ out)
{
    __shared__ float red[512];
    const int tid = threadIdx.x;
    float* p = out + (size_t)blockIdx.x * VV;
    const float4* p4 = (const float4*)p;
    const int n4 = VV / 4;

    float m = -1e30f;
    for (int i = tid; i < n4; i += 512) {
        float4 v = p4[i];
        m = fmaxf(m, fmaxf(fmaxf(v.x, v.y), fmaxf(v.z, v.w)));
    }
    red[tid] = m; __syncthreads();
    for (int s = 256; s > 0; s >>= 1) {
        if (tid < s) red[tid] = fmaxf(red[tid], red[tid + s]);
        __syncthreads();
    }
    m = red[0]; __syncthreads();

    float sum = 0.f;
    for (int i = tid; i < n4; i += 512) {
        float4 v = p4[i];
        sum += expf(v.x - m) + expf(v.y - m) + expf(v.z - m) + expf(v.w - m);
    }
    red[tid] = sum; __syncthreads();
    for (int s = 256; s > 0; s >>= 1) {
        if (tid < s) red[tid] += red[tid + s];
        __syncthreads();
    }
    const float L = m + logf(red[0]);

    float4* w4 = (float4*)p;
    for (int i = tid; i < n4; i += 512) {
        float4 v = w4[i];
        v.x -= L; v.y -= L; v.z -= L; v.w -= L;
        w4[i] = v;
    }
}

// K5: append h_final (t=31 odd -> g_h1), fp32
__global__ void hfinal_kernel(float* __restrict__ out)
{
    int i = blockIdx.x * blockDim.x + threadIdx.x;
    if (i < BB * HH) out[(size_t)BB * TT * VV + i] = g_h1[i];
}

// =====================================================================
extern "C" void kernel_launch(void* const* d_in, const int* in_sizes, int n_in,
                              void* d_out, int out_size)
{
    const void* enc_hidden = nullptr;
    const int*  target     = nullptr;
    const int*  sos        = nullptr;
    const void* emb        = nullptr;
    const void* outW       = nullptr;
    const void* Wih        = nullptr;
    const void* Whh        = nullptr;
    const void* bih        = nullptr;
    const void* bhh        = nullptr;
    const void* outb       = nullptr;

    for (int i = 0; i < n_in; i++) {
        int s = in_sizes[i];
        void* p = d_in[i];
        switch (s) {
            case 65536:     if (!enc_hidden) enc_hidden = p; break;
            case 2048:      target = (const int*)p; break;
            case 1:         if (!sos) sos = (const int*)p; break;
            case 32768000:  if (!emb) emb = p; else outW = p; break;
            case 3145728:   if (!Wih) Wih = p; else Whh = p; break;
            case 3072:      if (!bih) bih = p; else bhh = p; break;
            case 32000:     outb = p; break;
            default: break;
        }
    }
    float* out = (float*)d_out;
    if (!enc_hidden || !target || !emb || !outW || !Wih || !Whh || !bih || !bhh || !outb)
        return;

    detect_kernel<<<1, 32>>>(emb, target);
    init_h_kernel<<<(BB * HH + 255) / 256, 256>>>(enc_hidden);

    // out_W -> bf16 (overlaps with gi/GRU chain in the HW queue)
    conv_w_kernel<<<(int)(((size_t)VV * HH / 8 + 255) / 256), 256>>>(outW);

    // x rows (fp32) for tf32 gi
    build_xf_kernel<<<(int)(((size_t)MM * HH / 8 + 255) / 256), 256>>>(emb, target, sos);

    // gi GEMM via tf32 tensor cores
    {
        dim3 grid(GG / 128, MM / 128);  // 24 x 16
        gi_tf32_kernel<<<grid, 256>>>(Wih, bih);
    }

    // 32 sequential GRU steps (writes fp32 g_hs)
    for (int t = 0; t < TT; t++) {
        gru_step_v3<<<HH / 8, 512>>>(Whh, bhh, t);
    }

    // hs -> bf16 (proven path)
    conv_hs_kernel<<<(int)(((size_t)BB * TT * HH / 8 + 255) / 256), 256>>>();

    // projection via tensor cores -> d_out fp32 logits (proven R15)
    {
        dim3 grid(VV / 128, MM / 128);  // 250 x 16
        out_mma_kernel<<<grid, 256>>>(outb, out);
    }

    // in-place log_softmax
    logsoftmax_kernel<<<MM, 512>>>(out);

    if (out_size >= BB * TT * VV + BB * HH) {
        hfinal_kernel<<<(BB * HH + 255) / 256, 256>>>(out);
    }
}